// round 2
// baseline (speedup 1.0000x reference)
#include <cuda_runtime.h>
#include <math.h>

#define T_SEQ 2049
#define D_MODEL 1024
#define NH 16
#define HD 64
#define LOG2E 1.4426950408889634f

// Scratch (allocation-free rule: __device__ globals)
__device__ float g_qh[NH * T_SEQ * HD];
__device__ float g_kh[NH * T_SEQ * HD];
__device__ float g_vh[NH * T_SEQ * HD];
__device__ float g_ctx[T_SEQ * D_MODEL];

// ---------------------------------------------------------------------------
// Projection GEMM: out = x @ W^T + b, written head-major (H, T, HD)
// 64x64 tile, BK=16, 256 threads, 4x4 per thread.
// ---------------------------------------------------------------------------
__global__ __launch_bounds__(256) void proj_kernel(
    const float* __restrict__ q, const float* __restrict__ k, const float* __restrict__ v,
    const float* __restrict__ Wq, const float* __restrict__ Wk, const float* __restrict__ Wv,
    const float* __restrict__ bq, const float* __restrict__ bk, const float* __restrict__ bv)
{
    __shared__ float As[16][68];
    __shared__ float Bs[16][68];

    int z = blockIdx.z;
    const float* A    = (z == 0) ? q  : (z == 1) ? k  : v;
    const float* W    = (z == 0) ? Wq : (z == 1) ? Wk : Wv;
    const float* bias = (z == 0) ? bq : (z == 1) ? bk : bv;
    float* out        = (z == 0) ? g_qh : (z == 1) ? g_kh : g_vh;

    int m0 = blockIdx.x * 64, n0 = blockIdx.y * 64;
    int tid = threadIdx.x;
    int tx = tid & 15, ty = tid >> 4;
    int lr = tid >> 2, lc = tid & 3;

    float acc[4][4] = {};

    for (int k0 = 0; k0 < D_MODEL; k0 += 16) {
        int gr = m0 + lr;
        float4 a = make_float4(0.f, 0.f, 0.f, 0.f);
        if (gr < T_SEQ) a = *(const float4*)(A + (size_t)gr * D_MODEL + k0 + lc * 4);
        As[lc*4+0][lr] = a.x; As[lc*4+1][lr] = a.y; As[lc*4+2][lr] = a.z; As[lc*4+3][lr] = a.w;
        float4 b = *(const float4*)(W + (size_t)(n0 + lr) * D_MODEL + k0 + lc * 4);
        Bs[lc*4+0][lr] = b.x; Bs[lc*4+1][lr] = b.y; Bs[lc*4+2][lr] = b.z; Bs[lc*4+3][lr] = b.w;
        __syncthreads();
        #pragma unroll
        for (int kk = 0; kk < 16; kk++) {
            float a4[4], b4[4];
            *(float4*)a4 = *(const float4*)&As[kk][ty * 4];
            *(float4*)b4 = *(const float4*)&Bs[kk][tx * 4];
            #pragma unroll
            for (int i = 0; i < 4; i++)
                #pragma unroll
                for (int j = 0; j < 4; j++)
                    acc[i][j] = fmaf(a4[i], b4[j], acc[i][j]);
        }
        __syncthreads();
    }

    #pragma unroll
    for (int i = 0; i < 4; i++) {
        int t = m0 + ty * 4 + i;
        if (t >= T_SEQ) continue;
        #pragma unroll
        for (int j = 0; j < 4; j++) {
            int n = n0 + tx * 4 + j;
            out[(n >> 6) * (T_SEQ * HD) + t * HD + (n & 63)] = acc[i][j] + bias[n];
        }
    }
}

// ---------------------------------------------------------------------------
// Output GEMM: d_out = ctx @ Wo^T + bo  (row-major T x 1024)
// ---------------------------------------------------------------------------
__global__ __launch_bounds__(256) void out_kernel(
    const float* __restrict__ Wo, const float* __restrict__ bo, float* __restrict__ out)
{
    __shared__ float As[16][68];
    __shared__ float Bs[16][68];

    int m0 = blockIdx.x * 64, n0 = blockIdx.y * 64;
    int tid = threadIdx.x;
    int tx = tid & 15, ty = tid >> 4;
    int lr = tid >> 2, lc = tid & 3;

    float acc[4][4] = {};

    for (int k0 = 0; k0 < D_MODEL; k0 += 16) {
        int gr = m0 + lr;
        float4 a = make_float4(0.f, 0.f, 0.f, 0.f);
        if (gr < T_SEQ) a = *(const float4*)(g_ctx + (size_t)gr * D_MODEL + k0 + lc * 4);
        As[lc*4+0][lr] = a.x; As[lc*4+1][lr] = a.y; As[lc*4+2][lr] = a.z; As[lc*4+3][lr] = a.w;
        float4 b = *(const float4*)(Wo + (size_t)(n0 + lr) * D_MODEL + k0 + lc * 4);
        Bs[lc*4+0][lr] = b.x; Bs[lc*4+1][lr] = b.y; Bs[lc*4+2][lr] = b.z; Bs[lc*4+3][lr] = b.w;
        __syncthreads();
        #pragma unroll
        for (int kk = 0; kk < 16; kk++) {
            float a4[4], b4[4];
            *(float4*)a4 = *(const float4*)&As[kk][ty * 4];
            *(float4*)b4 = *(const float4*)&Bs[kk][tx * 4];
            #pragma unroll
            for (int i = 0; i < 4; i++)
                #pragma unroll
                for (int j = 0; j < 4; j++)
                    acc[i][j] = fmaf(a4[i], b4[j], acc[i][j]);
        }
        __syncthreads();
    }

    #pragma unroll
    for (int i = 0; i < 4; i++) {
        int t = m0 + ty * 4 + i;
        if (t >= T_SEQ) continue;
        float4 r;
        r.x = acc[i][0] + bo[n0 + tx*4 + 0];
        r.y = acc[i][1] + bo[n0 + tx*4 + 1];
        r.z = acc[i][2] + bo[n0 + tx*4 + 2];
        r.w = acc[i][3] + bo[n0 + tx*4 + 3];
        *(float4*)(out + (size_t)t * D_MODEL + n0 + tx * 4) = r;
    }
}

// ---------------------------------------------------------------------------
// Fused flash attention with relative-position bias.
// One block = one head x 64-query tile. Score tile:
//   S[r][c] = Q[r]·K[c] + Q[r+1]·Er[c]   (relative shift; Q row 64 of the
//   65-row Q smem tile covers the +1 shift; zero-padded at seq end)
// Online softmax (scale 1/8 pre-applied), causal mask, P·V accumulation.
// ---------------------------------------------------------------------------
#define ATTN_SMEM (5 * 64 * 68 * 4)

extern "C" __global__ __launch_bounds__(256) void attn_kernel(const float* __restrict__ Er)
{
    extern __shared__ float sm[];
    float* Qt = sm;               // [64 kd][68] rows 0..64 used (65 q-rows, transposed)
    float* Kt = Qt + 64 * 68;     // [64 kd][68] transposed
    float* Et = Kt + 64 * 68;     // [64 kd][68] transposed
    float* Vs = Et + 64 * 68;     // [64 key][68] natural
    float* Ps = Vs + 64 * 68;     // [64 row][68] probabilities

    int qi = blockIdx.x, h = blockIdx.y;
    int q0 = qi * 64;
    int tid = threadIdx.x;
    int tx = tid & 15, ty = tid >> 4;
    int c4 = tid & 15;            // float4 column index (0..15 -> cols c4*4..c4*4+3)
    int r16 = tid >> 4;           // row group base (0..15)

    const float* qh = g_qh + (size_t)h * (T_SEQ * HD);
    const float* kh = g_kh + (size_t)h * (T_SEQ * HD);
    const float* vh = g_vh + (size_t)h * (T_SEQ * HD);

    // Load Q tile (65 rows: q0 .. q0+64), transposed [kd][row]
    #pragma unroll
    for (int it = 0; it < 4; it++) {
        int row = r16 + it * 16;                       // 0..63
        int gr = q0 + row;
        float4 a = make_float4(0.f, 0.f, 0.f, 0.f);
        if (gr < T_SEQ) a = *(const float4*)(qh + (size_t)gr * HD + c4 * 4);
        Qt[(c4*4+0)*68 + row] = a.x; Qt[(c4*4+1)*68 + row] = a.y;
        Qt[(c4*4+2)*68 + row] = a.z; Qt[(c4*4+3)*68 + row] = a.w;
    }
    if (tid < 16) {
        int gr2 = q0 + 64;
        float4 b = make_float4(0.f, 0.f, 0.f, 0.f);
        if (gr2 < T_SEQ) b = *(const float4*)(qh + (size_t)gr2 * HD + tid * 4);
        Qt[(tid*4+0)*68 + 64] = b.x; Qt[(tid*4+1)*68 + 64] = b.y;
        Qt[(tid*4+2)*68 + 64] = b.z; Qt[(tid*4+3)*68 + 64] = b.w;
    }

    float m[4], l[4], o[4][4];
    #pragma unroll
    for (int i = 0; i < 4; i++) {
        m[i] = -1e30f; l[i] = 0.f;
        #pragma unroll
        for (int j = 0; j < 4; j++) o[i][j] = 0.f;
    }

    int q_hi = min(q0 + 63, T_SEQ - 1);
    int nkt = q_hi / 64 + 1;

    for (int kt = 0; kt < nkt; kt++) {
        int k0 = kt * 64;
        __syncthreads();  // prior PV reads done (also covers initial Qt fill)

        // Load K/Er (transposed) and V (natural): 64 rows x 64 cols each
        #pragma unroll
        for (int it = 0; it < 4; it++) {
            int row = r16 + it * 16;                   // 0..63
            int gc = k0 + row;
            float4 a = make_float4(0.f, 0.f, 0.f, 0.f);
            float4 e = a, vv = a;
            if (gc < T_SEQ) {
                a  = *(const float4*)(kh + (size_t)gc * HD + c4 * 4);
                e  = *(const float4*)(Er + (size_t)gc * HD + c4 * 4);
                vv = *(const float4*)(vh + (size_t)gc * HD + c4 * 4);
            }
            Kt[(c4*4+0)*68 + row] = a.x; Kt[(c4*4+1)*68 + row] = a.y;
            Kt[(c4*4+2)*68 + row] = a.z; Kt[(c4*4+3)*68 + row] = a.w;
            Et[(c4*4+0)*68 + row] = e.x; Et[(c4*4+1)*68 + row] = e.y;
            Et[(c4*4+2)*68 + row] = e.z; Et[(c4*4+3)*68 + row] = e.w;
            *(float4*)&Vs[row * 68 + c4 * 4] = vv;
        }
        __syncthreads();

        // S = Q K^T + Qshift Er^T
        float s[4][4] = {};
        #pragma unroll 8
        for (int kd = 0; kd < 64; kd++) {
            float qv[4], kv[4], ev[4];
            *(float4*)qv = *(const float4*)&Qt[kd * 68 + ty * 4];
            float q5 = Qt[kd * 68 + ty * 4 + 4];
            *(float4*)kv = *(const float4*)&Kt[kd * 68 + tx * 4];
            *(float4*)ev = *(const float4*)&Et[kd * 68 + tx * 4];
            #pragma unroll
            for (int i = 0; i < 4; i++) {
                float qs = (i < 3) ? qv[i + 1] : q5;
                #pragma unroll
                for (int j = 0; j < 4; j++) {
                    s[i][j] = fmaf(qv[i], kv[j], s[i][j]);
                    s[i][j] = fmaf(qs,    ev[j], s[i][j]);
                }
            }
        }

        // Mask + online softmax (scale = 1/sqrt(64) = 0.125)
        #pragma unroll
        for (int i = 0; i < 4; i++) {
            int gr = q0 + ty * 4 + i;
            float mx = -1e30f;
            #pragma unroll
            for (int j = 0; j < 4; j++) {
                int gc = k0 + tx * 4 + j;
                float sv = s[i][j] * 0.125f;
                if (gc > gr || gc >= T_SEQ) sv = -1e30f;
                s[i][j] = sv;
                mx = fmaxf(mx, sv);
            }
            #pragma unroll
            for (int off = 1; off < 16; off <<= 1)
                mx = fmaxf(mx, __shfl_xor_sync(0xffffffffu, mx, off));
            float mn = fmaxf(m[i], mx);
            float alpha = exp2f((m[i] - mn) * LOG2E);
            m[i] = mn;
            float e4[4];
            float sum = 0.f;
            #pragma unroll
            for (int j = 0; j < 4; j++) {
                float ev2 = exp2f((s[i][j] - mn) * LOG2E);
                e4[j] = ev2; sum += ev2;
            }
            #pragma unroll
            for (int off = 1; off < 16; off <<= 1)
                sum += __shfl_xor_sync(0xffffffffu, sum, off);
            l[i] = l[i] * alpha + sum;
            #pragma unroll
            for (int j = 0; j < 4; j++) o[i][j] *= alpha;
            *(float4*)&Ps[(ty * 4 + i) * 68 + tx * 4] = make_float4(e4[0], e4[1], e4[2], e4[3]);
        }
        __syncthreads();

        // O += P V
        #pragma unroll 8
        for (int kc = 0; kc < 64; kc++) {
            float4 vv = *(const float4*)&Vs[kc * 68 + tx * 4];
            #pragma unroll
            for (int i = 0; i < 4; i++) {
                float p = Ps[(ty * 4 + i) * 68 + kc];
                o[i][0] = fmaf(p, vv.x, o[i][0]);
                o[i][1] = fmaf(p, vv.y, o[i][1]);
                o[i][2] = fmaf(p, vv.z, o[i][2]);
                o[i][3] = fmaf(p, vv.w, o[i][3]);
            }
        }
    }

    // Normalize and write ctx (T, D) with d = h*64 + hd
    #pragma unroll
    for (int i = 0; i < 4; i++) {
        int gr = q0 + ty * 4 + i;
        if (gr < T_SEQ) {
            float inv = 1.0f / l[i];
            float4 r;
            r.x = o[i][0] * inv; r.y = o[i][1] * inv;
            r.z = o[i][2] * inv; r.w = o[i][3] * inv;
            *(float4*)&g_ctx[(size_t)gr * D_MODEL + h * HD + tx * 4] = r;
        }
    }
}

// ---------------------------------------------------------------------------
extern "C" void kernel_launch(void* const* d_in, const int* in_sizes, int n_in,
                              void* d_out, int out_size)
{
    const float* q  = (const float*)d_in[0];
    const float* k  = (const float*)d_in[1];
    const float* v  = (const float*)d_in[2];
    // d_in[3] = mask (int32 causal tril) — implied by the kernel, unused
    const float* Wq = (const float*)d_in[4];
    const float* bq = (const float*)d_in[5];
    const float* Wk = (const float*)d_in[6];
    const float* bk = (const float*)d_in[7];
    const float* Wv = (const float*)d_in[8];
    const float* bv = (const float*)d_in[9];
    const float* Er = (const float*)d_in[10];
    const float* Wo = (const float*)d_in[11];
    const float* bo = (const float*)d_in[12];
    float* out = (float*)d_out;

    cudaFuncSetAttribute(attn_kernel, cudaFuncAttributeMaxDynamicSharedMemorySize, ATTN_SMEM);

    dim3 gproj(33, 16, 3);             // ceil(2049/64) x (1024/64) x {q,k,v}
    proj_kernel<<<gproj, 256>>>(q, k, v, Wq, Wk, Wv, bq, bk, bv);

    dim3 gattn(33, NH);                // q-tiles x heads
    attn_kernel<<<gattn, 256, ATTN_SMEM>>>(Er);

    dim3 gout(33, 16);
    out_kernel<<<gout, 256>>>(Wo, bo, out);
}

// round 7
// speedup vs baseline: 1.2119x; 1.2119x over previous
#include <cuda_runtime.h>
#include <cuda_bf16.h>
#include <math.h>
#include <stdint.h>

#define T_SEQ 2049
#define D_MODEL 1024
#define NH 16
#define HD 64
#define LOG2E 1.4426950408889634f

// ---------------------------------------------------------------------------
// Scratch (__device__ globals; allocation-free rule)
// ---------------------------------------------------------------------------
__device__ __align__(128) float g_qh[NH * T_SEQ * HD];
__device__ __align__(128) float g_kh[NH * T_SEQ * HD];
__device__ __align__(128) float g_vh[NH * T_SEQ * HD];
__device__ __align__(128) float g_ctx[T_SEQ * D_MODEL];

// bf16 hi/lo decompositions
__device__ __align__(128) __nv_bfloat16 g_x_hi[3 * T_SEQ * D_MODEL];
__device__ __align__(128) __nv_bfloat16 g_x_lo[3 * T_SEQ * D_MODEL];
__device__ __align__(128) __nv_bfloat16 g_w_hi[4 * D_MODEL * D_MODEL];
__device__ __align__(128) __nv_bfloat16 g_w_lo[4 * D_MODEL * D_MODEL];
__device__ __align__(128) __nv_bfloat16 g_c_hi[T_SEQ * D_MODEL];
__device__ __align__(128) __nv_bfloat16 g_c_lo[T_SEQ * D_MODEL];

// ---------------------------------------------------------------------------
// Helpers (all plain sm_80+ PTX: cp.async / ldmatrix / mma.sync)
// ---------------------------------------------------------------------------
__device__ __forceinline__ uint32_t s2u(const void* p) {
    return (uint32_t)__cvta_generic_to_shared(p);
}
__device__ __forceinline__ void cp16(uint32_t s, const void* g) {
    asm volatile("cp.async.cg.shared.global [%0], [%1], 16;" :: "r"(s), "l"(g));
}
#define CP_COMMIT() asm volatile("cp.async.commit_group;" ::: "memory")
#define CP_WAIT(n)  asm volatile("cp.async.wait_group %0;" :: "n"(n) : "memory")

#define LDSM_X4(r0, r1, r2, r3, addr) \
    asm volatile("ldmatrix.sync.aligned.m8n8.x4.shared.b16 {%0,%1,%2,%3}, [%4];" \
        : "=r"(r0), "=r"(r1), "=r"(r2), "=r"(r3) : "r"(addr))
#define LDSM_X2(r0, r1, addr) \
    asm volatile("ldmatrix.sync.aligned.m8n8.x2.shared.b16 {%0,%1}, [%2];" \
        : "=r"(r0), "=r"(r1) : "r"(addr))

#define MMA_BF16(d, a, b) \
    asm volatile("mma.sync.aligned.m16n8k16.row.col.f32.bf16.bf16.f32 " \
        "{%0,%1,%2,%3}, {%4,%5,%6,%7}, {%8,%9}, {%0,%1,%2,%3};" \
        : "+f"((d)[0]), "+f"((d)[1]), "+f"((d)[2]), "+f"((d)[3]) \
        : "r"((a)[0]), "r"((a)[1]), "r"((a)[2]), "r"((a)[3]), \
          "r"((b)[0]), "r"((b)[1]))

// ---------------------------------------------------------------------------
// fp32 -> bf16 hi/lo conversion (n divisible by 4)
// ---------------------------------------------------------------------------
__global__ __launch_bounds__(256) void cvt_kernel(const float* __restrict__ s,
                                                  __nv_bfloat16* __restrict__ hi,
                                                  __nv_bfloat16* __restrict__ lo, int n) {
    int i = (blockIdx.x * 256 + threadIdx.x) * 4;
    if (i >= n) return;
    float4 v = *(const float4*)(s + i);
    __nv_bfloat16 h0 = __float2bfloat16(v.x);
    __nv_bfloat16 h1 = __float2bfloat16(v.y);
    __nv_bfloat16 h2 = __float2bfloat16(v.z);
    __nv_bfloat16 h3 = __float2bfloat16(v.w);
    __nv_bfloat16 l0 = __float2bfloat16(v.x - __bfloat162float(h0));
    __nv_bfloat16 l1 = __float2bfloat16(v.y - __bfloat162float(h1));
    __nv_bfloat16 l2 = __float2bfloat16(v.z - __bfloat162float(h2));
    __nv_bfloat16 l3 = __float2bfloat16(v.w - __bfloat162float(h3));
    __nv_bfloat162* hp = (__nv_bfloat162*)(hi + i);
    __nv_bfloat162* lp = (__nv_bfloat162*)(lo + i);
    hp[0] = __nv_bfloat162(h0, h1); hp[1] = __nv_bfloat162(h2, h3);
    lp[0] = __nv_bfloat162(l0, l1); lp[1] = __nv_bfloat162(l2, l3);
}

// ---------------------------------------------------------------------------
// HMMA GEMM: D[m,n] = sum_k A[m,k]*B[n,k] + bias[n]
//   bf16 split: Ah*Bh + Ah*Bl + Al*Bh  (3 terms x 16 k-chunks of 64 = 48 iters)
// 128x128 CTA tile, BK=64, 256 threads (8 warps, 2x4), cp.async double buffer.
// smem tiles padded to 144B rows (conflict-free ldmatrix).
// mode 0: proj (z = q/k/v) -> head-major g_qh/g_kh/g_vh
// mode 1: out-proj -> row-major out_param
// ---------------------------------------------------------------------------
#define ROWB 144                         // padded row stride, bytes (64 bf16 + 8 pad)
#define TILEB (128 * ROWB)               // 18432 bytes per operand tile
#define GEMM_SMEM (4 * TILEB)            // A0,B0,A1,B1 = 73728
#define NIT 48

__global__ __launch_bounds__(256) void gemm_tc_kernel(
    const float* __restrict__ bias0, const float* __restrict__ bias1,
    const float* __restrict__ bias2, float* __restrict__ out_param, int mode)
{
    extern __shared__ __align__(128) char smem[];
    const uint32_t smem_base = s2u(smem);
    const int tid = threadIdx.x;
    const int wid = tid >> 5, lane = tid & 31;
    const int wm = (wid & 1) * 64;       // warp M offset in tile
    const int wn = (wid >> 1) * 32;      // warp N offset in tile
    const int m0 = blockIdx.x * 128, n0 = blockIdx.y * 128;

    const __nv_bfloat16 *Ah, *Al, *Bh, *Bl;
    const float* bias;
    float* outp;
    const size_t S = (size_t)T_SEQ * D_MODEL, DD = (size_t)D_MODEL * D_MODEL;
    if (mode == 0) {
        int z = blockIdx.z;
        Ah = g_x_hi + z * S; Al = g_x_lo + z * S;
        Bh = g_w_hi + z * DD; Bl = g_w_lo + z * DD;
        bias = (z == 0) ? bias0 : (z == 1) ? bias1 : bias2;
        outp = (z == 0) ? g_qh : (z == 1) ? g_kh : g_vh;
    } else {
        Ah = g_c_hi; Al = g_c_lo;
        Bh = g_w_hi + 3 * DD; Bl = g_w_lo + 3 * DD;
        bias = bias0;
        outp = out_param;
    }
    const __nv_bfloat16* APtr[3] = { Ah, Ah, Al };
    const __nv_bfloat16* BPtr[3] = { Bh, Bl, Bh };

    // ---- load mapping: 2 threads per row, 4 x 16B chunks each ----
    const int lrow = tid >> 1;                 // 0..127
    const int lc = (tid & 1) * 4;              // chunk base (0 or 4)
    int tA = m0 + lrow; if (tA > T_SEQ - 1) tA = T_SEQ - 1;   // clamp (writes guarded)
    const size_t a_base = (size_t)tA * D_MODEL + lc * 8;
    const size_t b_base = (size_t)(n0 + lrow) * D_MODEL + lc * 8;
    const uint32_t s_off = (uint32_t)lrow * ROWB + lc * 16;

    float acc[4][4][4] = {};

    // prologue: stage 0 <- iteration 0
    {
        const __nv_bfloat16* ga = APtr[0] + a_base;
        const __nv_bfloat16* gb = BPtr[0] + b_base;
        uint32_t sa = smem_base + s_off, sb = sa + TILEB;
        #pragma unroll
        for (int j = 0; j < 4; j++) { cp16(sa + j * 16, ga + j * 8); cp16(sb + j * 16, gb + j * 8); }
        CP_COMMIT();
    }

    for (int it = 0; it < NIT; it++) {
        const int cur = it & 1;
        if (it + 1 < NIT) {
            const int nit = it + 1, ns = nit & 1;
            const int term = nit >> 4, k0 = (nit & 15) * 64;
            const __nv_bfloat16* ga = APtr[term] + a_base + k0;
            const __nv_bfloat16* gb = BPtr[term] + b_base + k0;
            uint32_t sa = smem_base + ns * (2 * TILEB) + s_off, sb = sa + TILEB;
            #pragma unroll
            for (int j = 0; j < 4; j++) { cp16(sa + j * 16, ga + j * 8); cp16(sb + j * 16, gb + j * 8); }
            CP_COMMIT();
            CP_WAIT(1);
        } else {
            CP_WAIT(0);
        }
        __syncthreads();

        // ---- compute on stage `cur` ----
        const uint32_t saA = smem_base + cur * (2 * TILEB);
        const uint32_t saB = saA + TILEB;
        const uint32_t aBase = saA + (uint32_t)(wm + (lane & 15)) * ROWB + (lane >> 4) * 16;
        const uint32_t bBase = saB + (uint32_t)(wn + (lane & 7)) * ROWB + ((lane >> 3) & 1) * 16;

        #pragma unroll
        for (int ks = 0; ks < 4; ks++) {
            uint32_t a[4][4];
            #pragma unroll
            for (int mi = 0; mi < 4; mi++)
                LDSM_X4(a[mi][0], a[mi][1], a[mi][2], a[mi][3],
                        aBase + mi * (16 * ROWB) + ks * 32);
            uint32_t b[4][2];
            #pragma unroll
            for (int ni = 0; ni < 4; ni++)
                LDSM_X2(b[ni][0], b[ni][1], bBase + ni * (8 * ROWB) + ks * 32);
            #pragma unroll
            for (int mi = 0; mi < 4; mi++)
                #pragma unroll
                for (int ni = 0; ni < 4; ni++)
                    MMA_BF16(acc[mi][ni], a[mi], b[ni]);
        }
        __syncthreads();
    }

    // ---- epilogue: fragment (mi,ni): rows wm+mi*16+lane/4 (+8), cols wn+ni*8+(lane%4)*2 ----
    const int r_in = lane >> 2, c_in = (lane & 3) * 2;
    #pragma unroll
    for (int mi = 0; mi < 4; mi++) {
        #pragma unroll
        for (int half = 0; half < 2; half++) {
            int t = m0 + wm + mi * 16 + r_in + half * 8;
            if (t >= T_SEQ) continue;
            #pragma unroll
            for (int ni = 0; ni < 4; ni++) {
                int n = n0 + wn + ni * 8 + c_in;
                float v0 = acc[mi][ni][half * 2 + 0] + bias[n];
                float v1 = acc[mi][ni][half * 2 + 1] + bias[n + 1];
                if (mode == 0) {
                    float* dst = outp + (size_t)(n >> 6) * (T_SEQ * HD)
                                      + (size_t)t * HD + (n & 63);
                    dst[0] = v0; dst[1] = v1;
                } else {
                    float* dst = outp + (size_t)t * D_MODEL + n;
                    dst[0] = v0; dst[1] = v1;
                }
            }
        }
    }
}

// ---------------------------------------------------------------------------
// Fused flash attention with relative-position bias (unchanged from R2 pass).
// ---------------------------------------------------------------------------
#define ATTN_SMEM (5 * 64 * 68 * 4)

extern "C" __global__ __launch_bounds__(256) void attn_kernel(const float* __restrict__ Er)
{
    extern __shared__ float sm[];
    float* Qt = sm;               // [64 kd][68] rows 0..64 used (65 q-rows, transposed)
    float* Kt = Qt + 64 * 68;
    float* Et = Kt + 64 * 68;
    float* Vs = Et + 64 * 68;
    float* Ps = Vs + 64 * 68;

    int qi = blockIdx.x, h = blockIdx.y;
    int q0 = qi * 64;
    int tid = threadIdx.x;
    int tx = tid & 15, ty = tid >> 4;
    int c4 = tid & 15;
    int r16 = tid >> 4;

    const float* qh = g_qh + (size_t)h * (T_SEQ * HD);
    const float* kh = g_kh + (size_t)h * (T_SEQ * HD);
    const float* vh = g_vh + (size_t)h * (T_SEQ * HD);

    #pragma unroll
    for (int it = 0; it < 4; it++) {
        int row = r16 + it * 16;
        int gr = q0 + row;
        float4 a = make_float4(0.f, 0.f, 0.f, 0.f);
        if (gr < T_SEQ) a = *(const float4*)(qh + (size_t)gr * HD + c4 * 4);
        Qt[(c4*4+0)*68 + row] = a.x; Qt[(c4*4+1)*68 + row] = a.y;
        Qt[(c4*4+2)*68 + row] = a.z; Qt[(c4*4+3)*68 + row] = a.w;
    }
    if (tid < 16) {
        int gr2 = q0 + 64;
        float4 b = make_float4(0.f, 0.f, 0.f, 0.f);
        if (gr2 < T_SEQ) b = *(const float4*)(qh + (size_t)gr2 * HD + tid * 4);
        Qt[(tid*4+0)*68 + 64] = b.x; Qt[(tid*4+1)*68 + 64] = b.y;
        Qt[(tid*4+2)*68 + 64] = b.z; Qt[(tid*4+3)*68 + 64] = b.w;
    }

    float m[4], l[4], o[4][4];
    #pragma unroll
    for (int i = 0; i < 4; i++) {
        m[i] = -1e30f; l[i] = 0.f;
        #pragma unroll
        for (int j = 0; j < 4; j++) o[i][j] = 0.f;
    }

    int q_hi = min(q0 + 63, T_SEQ - 1);
    int nkt = q_hi / 64 + 1;

    for (int kt = 0; kt < nkt; kt++) {
        int k0 = kt * 64;
        __syncthreads();

        #pragma unroll
        for (int it = 0; it < 4; it++) {
            int row = r16 + it * 16;
            int gc = k0 + row;
            float4 a = make_float4(0.f, 0.f, 0.f, 0.f);
            float4 e = a, vv = a;
            if (gc < T_SEQ) {
                a  = *(const float4*)(kh + (size_t)gc * HD + c4 * 4);
                e  = *(const float4*)(Er + (size_t)gc * HD + c4 * 4);
                vv = *(const float4*)(vh + (size_t)gc * HD + c4 * 4);
            }
            Kt[(c4*4+0)*68 + row] = a.x; Kt[(c4*4+1)*68 + row] = a.y;
            Kt[(c4*4+2)*68 + row] = a.z; Kt[(c4*4+3)*68 + row] = a.w;
            Et[(c4*4+0)*68 + row] = e.x; Et[(c4*4+1)*68 + row] = e.y;
            Et[(c4*4+2)*68 + row] = e.z; Et[(c4*4+3)*68 + row] = e.w;
            *(float4*)&Vs[row * 68 + c4 * 4] = vv;
        }
        __syncthreads();

        float s[4][4] = {};
        #pragma unroll 8
        for (int kd = 0; kd < 64; kd++) {
            float qv[4], kv[4], ev[4];
            *(float4*)qv = *(const float4*)&Qt[kd * 68 + ty * 4];
            float q5 = Qt[kd * 68 + ty * 4 + 4];
            *(float4*)kv = *(const float4*)&Kt[kd * 68 + tx * 4];
            *(float4*)ev = *(const float4*)&Et[kd * 68 + tx * 4];
            #pragma unroll
            for (int i = 0; i < 4; i++) {
                float qs = (i < 3) ? qv[i + 1] : q5;
                #pragma unroll
                for (int j = 0; j < 4; j++) {
                    s[i][j] = fmaf(qv[i], kv[j], s[i][j]);
                    s[i][j] = fmaf(qs,    ev[j], s[i][j]);
                }
            }
        }

        #pragma unroll
        for (int i = 0; i < 4; i++) {
            int gr = q0 + ty * 4 + i;
            float mx = -1e30f;
            #pragma unroll
            for (int j = 0; j < 4; j++) {
                int gc = k0 + tx * 4 + j;
                float sv = s[i][j] * 0.125f;
                if (gc > gr || gc >= T_SEQ) sv = -1e30f;
                s[i][j] = sv;
                mx = fmaxf(mx, sv);
            }
            #pragma unroll
            for (int off = 1; off < 16; off <<= 1)
                mx = fmaxf(mx, __shfl_xor_sync(0xffffffffu, mx, off));
            float mn = fmaxf(m[i], mx);
            float alpha = exp2f((m[i] - mn) * LOG2E);
            m[i] = mn;
            float e4[4];
            float sum = 0.f;
            #pragma unroll
            for (int j = 0; j < 4; j++) {
                float ev2 = exp2f((s[i][j] - mn) * LOG2E);
                e4[j] = ev2; sum += ev2;
            }
            #pragma unroll
            for (int off = 1; off < 16; off <<= 1)
                sum += __shfl_xor_sync(0xffffffffu, sum, off);
            l[i] = l[i] * alpha + sum;
            #pragma unroll
            for (int j = 0; j < 4; j++) o[i][j] *= alpha;
            *(float4*)&Ps[(ty * 4 + i) * 68 + tx * 4] = make_float4(e4[0], e4[1], e4[2], e4[3]);
        }
        __syncthreads();

        #pragma unroll 8
        for (int kc = 0; kc < 64; kc++) {
            float4 vv = *(const float4*)&Vs[kc * 68 + tx * 4];
            #pragma unroll
            for (int i = 0; i < 4; i++) {
                float p = Ps[(ty * 4 + i) * 68 + kc];
                o[i][0] = fmaf(p, vv.x, o[i][0]);
                o[i][1] = fmaf(p, vv.y, o[i][1]);
                o[i][2] = fmaf(p, vv.z, o[i][2]);
                o[i][3] = fmaf(p, vv.w, o[i][3]);
            }
        }
    }

    #pragma unroll
    for (int i = 0; i < 4; i++) {
        int gr = q0 + ty * 4 + i;
        if (gr < T_SEQ) {
            float inv = 1.0f / l[i];
            float4 r;
            r.x = o[i][0] * inv; r.y = o[i][1] * inv;
            r.z = o[i][2] * inv; r.w = o[i][3] * inv;
            *(float4*)&g_ctx[(size_t)gr * D_MODEL + h * HD + tx * 4] = r;
        }
    }
}

// ---------------------------------------------------------------------------
extern "C" void kernel_launch(void* const* d_in, const int* in_sizes, int n_in,
                              void* d_out, int out_size)
{
    const float* q  = (const float*)d_in[0];
    const float* k  = (const float*)d_in[1];
    const float* v  = (const float*)d_in[2];
    // d_in[3] = mask (int32 causal tril) — implied by the kernel, unused
    const float* Wq = (const float*)d_in[4];
    const float* bq = (const float*)d_in[5];
    const float* Wk = (const float*)d_in[6];
    const float* bk = (const float*)d_in[7];
    const float* Wv = (const float*)d_in[8];
    const float* bv = (const float*)d_in[9];
    const float* Er = (const float*)d_in[10];
    const float* Wo = (const float*)d_in[11];
    const float* bo = (const float*)d_in[12];
    float* out = (float*)d_out;

    cudaFuncSetAttribute(attn_kernel, cudaFuncAttributeMaxDynamicSharedMemorySize, ATTN_SMEM);
    cudaFuncSetAttribute(gemm_tc_kernel, cudaFuncAttributeMaxDynamicSharedMemorySize, GEMM_SMEM);

    // device addresses of the bf16 scratch symbols
    __nv_bfloat16 *xh, *xl, *wh, *wl, *ch, *cl;
    float* ctxp;
    cudaGetSymbolAddress((void**)&xh, g_x_hi);
    cudaGetSymbolAddress((void**)&xl, g_x_lo);
    cudaGetSymbolAddress((void**)&wh, g_w_hi);
    cudaGetSymbolAddress((void**)&wl, g_w_lo);
    cudaGetSymbolAddress((void**)&ch, g_c_hi);
    cudaGetSymbolAddress((void**)&cl, g_c_lo);
    cudaGetSymbolAddress((void**)&ctxp, g_ctx);

    const int S = T_SEQ * D_MODEL;       // 2098176
    const int DD = D_MODEL * D_MODEL;    // 1048576
    int gS = (S / 4 + 255) / 256, gD = (DD / 4 + 255) / 256;

    // convert inputs
    cvt_kernel<<<gS, 256>>>(q, xh + 0 * (size_t)S, xl + 0 * (size_t)S, S);
    cvt_kernel<<<gS, 256>>>(k, xh + 1 * (size_t)S, xl + 1 * (size_t)S, S);
    cvt_kernel<<<gS, 256>>>(v, xh + 2 * (size_t)S, xl + 2 * (size_t)S, S);
    cvt_kernel<<<gD, 256>>>(Wq, wh + 0 * (size_t)DD, wl + 0 * (size_t)DD, DD);
    cvt_kernel<<<gD, 256>>>(Wk, wh + 1 * (size_t)DD, wl + 1 * (size_t)DD, DD);
    cvt_kernel<<<gD, 256>>>(Wv, wh + 2 * (size_t)DD, wl + 2 * (size_t)DD, DD);
    cvt_kernel<<<gD, 256>>>(Wo, wh + 3 * (size_t)DD, wl + 3 * (size_t)DD, DD);

    // QKV projections on tensor cores (17 M-tiles x 8 N-tiles x 3)
    dim3 gproj(17, 8, 3);
    gemm_tc_kernel<<<gproj, 256, GEMM_SMEM>>>(bq, bk, bv, nullptr, 0);

    // attention
    dim3 gattn(33, NH);
    attn_kernel<<<gattn, 256, ATTN_SMEM>>>(Er);

    // convert ctx, output projection
    cvt_kernel<<<gS, 256>>>(ctxp, ch, cl, S);
    dim3 gout(17, 8, 1);
    gemm_tc_kernel<<<gout, 256, GEMM_SMEM>>>(bo, nullptr, nullptr, out, 1);
}

// round 8
// speedup vs baseline: 2.0356x; 1.6797x over previous
#include <cuda_runtime.h>
#include <cuda_bf16.h>
#include <math.h>
#include <stdint.h>

#define T_SEQ 2049
#define D_MODEL 1024
#define NH 16
#define HD 64
#define LOG2E 1.4426950408889634f
#define SCALE_EXP 0.18033688011112042f   // 0.125 * log2(e)

// ---------------------------------------------------------------------------
// Scratch (__device__ globals; allocation-free rule)
// ---------------------------------------------------------------------------
__device__ __align__(128) __nv_bfloat16 g_x_hi[3 * T_SEQ * D_MODEL];
__device__ __align__(128) __nv_bfloat16 g_x_lo[3 * T_SEQ * D_MODEL];
__device__ __align__(128) __nv_bfloat16 g_w_hi[4 * D_MODEL * D_MODEL];
__device__ __align__(128) __nv_bfloat16 g_w_lo[4 * D_MODEL * D_MODEL];
__device__ __align__(128) __nv_bfloat16 g_c_hi[T_SEQ * D_MODEL];
__device__ __align__(128) __nv_bfloat16 g_c_lo[T_SEQ * D_MODEL];

__device__ __align__(128) __nv_bfloat16 g_qh_hi[NH * T_SEQ * HD];
__device__ __align__(128) __nv_bfloat16 g_qh_lo[NH * T_SEQ * HD];
__device__ __align__(128) __nv_bfloat16 g_kh_hi[NH * T_SEQ * HD];
__device__ __align__(128) __nv_bfloat16 g_kh_lo[NH * T_SEQ * HD];
__device__ __align__(128) __nv_bfloat16 g_vh_hi[NH * T_SEQ * HD];
__device__ __align__(128) __nv_bfloat16 g_vh_lo[NH * T_SEQ * HD];
__device__ __align__(128) __nv_bfloat16 g_er_hi[T_SEQ * HD];
__device__ __align__(128) __nv_bfloat16 g_er_lo[T_SEQ * HD];

// ---------------------------------------------------------------------------
// Helpers (all plain sm_80+ PTX: cp.async / ldmatrix / mma.sync)
// ---------------------------------------------------------------------------
__device__ __forceinline__ uint32_t s2u(const void* p) {
    return (uint32_t)__cvta_generic_to_shared(p);
}
__device__ __forceinline__ void cp16(uint32_t s, const void* g) {
    asm volatile("cp.async.cg.shared.global [%0], [%1], 16;" :: "r"(s), "l"(g));
}
__device__ __forceinline__ void cp16z(uint32_t s, const void* g, bool ok) {
    int sz = ok ? 16 : 0;
    asm volatile("cp.async.cg.shared.global [%0], [%1], 16, %2;" :: "r"(s), "l"(g), "r"(sz));
}
#define CP_COMMIT() asm volatile("cp.async.commit_group;" ::: "memory")
#define CP_WAIT(n)  asm volatile("cp.async.wait_group %0;" :: "n"(n) : "memory")

#define LDSM_X4(r0, r1, r2, r3, addr) \
    asm volatile("ldmatrix.sync.aligned.m8n8.x4.shared.b16 {%0,%1,%2,%3}, [%4];" \
        : "=r"(r0), "=r"(r1), "=r"(r2), "=r"(r3) : "r"(addr))
#define LDSM_X4T(r0, r1, r2, r3, addr) \
    asm volatile("ldmatrix.sync.aligned.m8n8.x4.trans.shared.b16 {%0,%1,%2,%3}, [%4];" \
        : "=r"(r0), "=r"(r1), "=r"(r2), "=r"(r3) : "r"(addr))
#define LDSM_X2(r0, r1, addr) \
    asm volatile("ldmatrix.sync.aligned.m8n8.x2.shared.b16 {%0,%1}, [%2];" \
        : "=r"(r0), "=r"(r1) : "r"(addr))

#define MMA_BF16(d, a, b) \
    asm volatile("mma.sync.aligned.m16n8k16.row.col.f32.bf16.bf16.f32 " \
        "{%0,%1,%2,%3}, {%4,%5,%6,%7}, {%8,%9}, {%0,%1,%2,%3};" \
        : "+f"((d)[0]), "+f"((d)[1]), "+f"((d)[2]), "+f"((d)[3]) \
        : "r"((a)[0]), "r"((a)[1]), "r"((a)[2]), "r"((a)[3]), \
          "r"((b)[0]), "r"((b)[1]))

__device__ __forceinline__ uint32_t packbf(float lo, float hi) {
    uint32_t d;
    asm("cvt.rn.bf16x2.f32 %0, %1, %2;" : "=r"(d) : "f"(hi), "f"(lo));
    return d;
}
__device__ __forceinline__ float bfr(float x) {      // round to bf16, back to f32
    return __bfloat162float(__float2bfloat16(x));
}

// ---------------------------------------------------------------------------
// fp32 -> bf16 hi/lo conversion (n divisible by 4)
// ---------------------------------------------------------------------------
__global__ __launch_bounds__(256) void cvt_kernel(const float* __restrict__ s,
                                                  __nv_bfloat16* __restrict__ hi,
                                                  __nv_bfloat16* __restrict__ lo, int n) {
    int i = (blockIdx.x * 256 + threadIdx.x) * 4;
    if (i >= n) return;
    float4 v = *(const float4*)(s + i);
    float h0 = bfr(v.x), h1 = bfr(v.y), h2 = bfr(v.z), h3 = bfr(v.w);
    uint32_t* hp = (uint32_t*)(hi + i);
    uint32_t* lp = (uint32_t*)(lo + i);
    hp[0] = packbf(h0, h1); hp[1] = packbf(h2, h3);
    lp[0] = packbf(v.x - h0, v.y - h1); lp[1] = packbf(v.z - h2, v.w - h3);
}

// ---------------------------------------------------------------------------
// HMMA GEMM: D[m,n] = sum_k A[m,k]*B[n,k] + bias[n]
//   bf16 split: Ah*Bh + Ah*Bl + Al*Bh  (3 terms x 16 k-chunks of 64 = 48 iters)
// mode 0: proj (z = q/k/v) -> head-major bf16 hi/lo (g_qh_hi/lo etc.)
// mode 1: out-proj -> fp32 row-major out_param
// ---------------------------------------------------------------------------
#define ROWB 144
#define TILEB (128 * ROWB)
#define GEMM_SMEM (4 * TILEB)
#define NIT 48

__global__ __launch_bounds__(256) void gemm_tc_kernel(
    const float* __restrict__ bias0, const float* __restrict__ bias1,
    const float* __restrict__ bias2, float* __restrict__ out_param, int mode)
{
    extern __shared__ __align__(128) char smem[];
    const uint32_t smem_base = s2u(smem);
    const int tid = threadIdx.x;
    const int wid = tid >> 5, lane = tid & 31;
    const int wm = (wid & 1) * 64;
    const int wn = (wid >> 1) * 32;
    const int m0 = blockIdx.x * 128, n0 = blockIdx.y * 128;

    const __nv_bfloat16 *Ah, *Al, *Bh, *Bl;
    const float* bias;
    float* outp = nullptr;
    __nv_bfloat16 *oh = nullptr, *ol = nullptr;
    const size_t S = (size_t)T_SEQ * D_MODEL, DD = (size_t)D_MODEL * D_MODEL;
    if (mode == 0) {
        int z = blockIdx.z;
        Ah = g_x_hi + z * S; Al = g_x_lo + z * S;
        Bh = g_w_hi + z * DD; Bl = g_w_lo + z * DD;
        bias = (z == 0) ? bias0 : (z == 1) ? bias1 : bias2;
        oh = (z == 0) ? g_qh_hi : (z == 1) ? g_kh_hi : g_vh_hi;
        ol = (z == 0) ? g_qh_lo : (z == 1) ? g_kh_lo : g_vh_lo;
    } else {
        Ah = g_c_hi; Al = g_c_lo;
        Bh = g_w_hi + 3 * DD; Bl = g_w_lo + 3 * DD;
        bias = bias0;
        outp = out_param;
    }
    const __nv_bfloat16* APtr[3] = { Ah, Ah, Al };
    const __nv_bfloat16* BPtr[3] = { Bh, Bl, Bh };

    const int lrow = tid >> 1;
    const int lc = (tid & 1) * 4;
    int tA = m0 + lrow; if (tA > T_SEQ - 1) tA = T_SEQ - 1;
    const size_t a_base = (size_t)tA * D_MODEL + lc * 8;
    const size_t b_base = (size_t)(n0 + lrow) * D_MODEL + lc * 8;
    const uint32_t s_off = (uint32_t)lrow * ROWB + lc * 16;

    float acc[4][4][4] = {};

    {
        const __nv_bfloat16* ga = APtr[0] + a_base;
        const __nv_bfloat16* gb = BPtr[0] + b_base;
        uint32_t sa = smem_base + s_off, sb = sa + TILEB;
        #pragma unroll
        for (int j = 0; j < 4; j++) { cp16(sa + j * 16, ga + j * 8); cp16(sb + j * 16, gb + j * 8); }
        CP_COMMIT();
    }

    for (int it = 0; it < NIT; it++) {
        const int cur = it & 1;
        if (it + 1 < NIT) {
            const int nit = it + 1, ns = nit & 1;
            const int term = nit >> 4, k0 = (nit & 15) * 64;
            const __nv_bfloat16* ga = APtr[term] + a_base + k0;
            const __nv_bfloat16* gb = BPtr[term] + b_base + k0;
            uint32_t sa = smem_base + ns * (2 * TILEB) + s_off, sb = sa + TILEB;
            #pragma unroll
            for (int j = 0; j < 4; j++) { cp16(sa + j * 16, ga + j * 8); cp16(sb + j * 16, gb + j * 8); }
            CP_COMMIT();
            CP_WAIT(1);
        } else {
            CP_WAIT(0);
        }
        __syncthreads();

        const uint32_t saA = smem_base + cur * (2 * TILEB);
        const uint32_t saB = saA + TILEB;
        const uint32_t aBase = saA + (uint32_t)(wm + (lane & 15)) * ROWB + (lane >> 4) * 16;
        const uint32_t bBase = saB + (uint32_t)(wn + (lane & 7)) * ROWB + ((lane >> 3) & 1) * 16;

        #pragma unroll
        for (int ks = 0; ks < 4; ks++) {
            uint32_t a[4][4];
            #pragma unroll
            for (int mi = 0; mi < 4; mi++)
                LDSM_X4(a[mi][0], a[mi][1], a[mi][2], a[mi][3],
                        aBase + mi * (16 * ROWB) + ks * 32);
            uint32_t b[4][2];
            #pragma unroll
            for (int ni = 0; ni < 4; ni++)
                LDSM_X2(b[ni][0], b[ni][1], bBase + ni * (8 * ROWB) + ks * 32);
            #pragma unroll
            for (int mi = 0; mi < 4; mi++)
                #pragma unroll
                for (int ni = 0; ni < 4; ni++)
                    MMA_BF16(acc[mi][ni], a[mi], b[ni]);
        }
        __syncthreads();
    }

    const int r_in = lane >> 2, c_in = (lane & 3) * 2;
    #pragma unroll
    for (int mi = 0; mi < 4; mi++) {
        #pragma unroll
        for (int half = 0; half < 2; half++) {
            int t = m0 + wm + mi * 16 + r_in + half * 8;
            if (t >= T_SEQ) continue;
            #pragma unroll
            for (int ni = 0; ni < 4; ni++) {
                int n = n0 + wn + ni * 8 + c_in;
                float v0 = acc[mi][ni][half * 2 + 0] + bias[n];
                float v1 = acc[mi][ni][half * 2 + 1] + bias[n + 1];
                if (mode == 0) {
                    size_t off = (size_t)(n >> 6) * (T_SEQ * HD) + (size_t)t * HD + (n & 63);
                    float h0 = bfr(v0), h1 = bfr(v1);
                    *(uint32_t*)(oh + off) = packbf(h0, h1);
                    *(uint32_t*)(ol + off) = packbf(v0 - h0, v1 - h1);
                } else {
                    float* dst = outp + (size_t)t * D_MODEL + n;
                    dst[0] = v0; dst[1] = v1;
                }
            }
        }
    }
}

// ---------------------------------------------------------------------------
// Tensor-core flash attention with relative-position bias.
// Block: one head x 128 q-rows (8 warps x 16 rows). Key tiles of 64.
// S = [Q | Qshift] . [K | Er]^T  (concat k=128; shift = A-frag at row+1),
// 3-term bf16 hi/lo split everywhere. Register softmax (FA2 layout),
// PV = Ph*Vh + Pl*Vh + Ph*Vl with ldmatrix.trans V fragments.
// Outputs ctx directly as bf16 hi/lo (g_c_hi / g_c_lo).
// ---------------------------------------------------------------------------
#define AT_QH 0
#define AT_QL 18720                 // 130 * 144
#define AT_T0 37440                 // K_hi,K_lo,E_hi,E_lo,V_hi,V_lo @ 9216 each
#define AT_VH (AT_T0 + 4 * 9216)
#define ATTN_SMEM 92736

__global__ __launch_bounds__(256, 2) void attn_tc_kernel()
{
    extern __shared__ __align__(128) char smem[];
    const uint32_t sb = s2u(smem);
    const int tid = threadIdx.x;
    const int wid = tid >> 5, lane = tid & 31;
    const int bid = blockIdx.x;
    const int qi = 16 - (bid >> 4);          // heavy tiles first
    const int h = bid & 15;
    const int q0 = qi * 128;
    const size_t hoff = (size_t)h * (T_SEQ * HD);

    // ---- Q tile: 129 rows, hi + lo, zero-filled past T ----
    for (int idx = tid; idx < 2 * 1032; idx += 256) {
        int half = (idx >= 1032) ? 1 : 0;
        int s_ = idx - half * 1032;
        int row = s_ >> 3, ch = s_ & 7;
        int gr = q0 + row;
        bool ok = gr < T_SEQ; if (!ok) gr = T_SEQ - 1;
        const __nv_bfloat16* src = (half ? g_qh_lo : g_qh_hi) + hoff + (size_t)gr * HD + ch * 8;
        cp16z(sb + (half ? AT_QL : AT_QH) + row * 144 + ch * 16, src, ok);
    }
    CP_COMMIT();

    const int r = lane >> 2, c2 = (lane & 3) * 2;
    const int grA = q0 + wid * 16 + r, grB = grA + 8;
    const uint32_t a_off = (uint32_t)(wid * 16 + (lane & 15)) * 144 + (lane >> 4) * 16;
    const uint32_t b_lane = (uint32_t)((lane & 7) + ((lane >> 4) & 1) * 8) * 144 + ((lane >> 3) & 1) * 16;
    const uint32_t v_lane = (uint32_t)((lane & 7) + ((lane >> 3) & 1) * 8) * 144 + ((lane >> 4) & 1) * 16;

    float o[8][4] = {};
    float mA = -1e30f, mB = -1e30f, lA = 0.f, lB = 0.f;

    const int kmax = min(q0 + 127, T_SEQ - 1);
    const int nkt = kmax / 64 + 1;
    const int wlimit = q0 + wid * 16 + 15;

    const __nv_bfloat16* srcs[6] = { g_kh_hi + hoff, g_kh_lo + hoff, g_er_hi, g_er_lo,
                                     g_vh_hi + hoff, g_vh_lo + hoff };

    for (int kt = 0; kt < nkt; kt++) {
        const int k0 = kt * 64;
        __syncthreads();                      // previous tile fully consumed
        for (int idx = tid; idx < 3072; idx += 256) {
            int tile = idx >> 9, sub = idx & 511, row = sub >> 3, ch = sub & 7;
            int gc = k0 + row; if (gc > T_SEQ - 1) gc = T_SEQ - 1;
            cp16(sb + AT_T0 + tile * 9216 + row * 144 + ch * 16,
                 srcs[tile] + (size_t)gc * HD + ch * 8);
        }
        CP_COMMIT(); CP_WAIT(0);
        __syncthreads();

        if (k0 > wlimit) continue;            // warp fully masked for this tile

        // ---- S accumulation: terms (Qh,Bh), (Qh,Bl), (Ql,Bh) ----
        float s[8][4] = {};
        // terms 0,1 share the Qh A fragments
        #pragma unroll
        for (int kc = 0; kc < 8; kc++) {
            uint32_t av[4];
            uint32_t aaddr = sb + AT_QH + a_off + ((kc < 4) ? kc * 32 : (kc - 4) * 32 + 144);
            LDSM_X4(av[0], av[1], av[2], av[3], aaddr);
            #pragma unroll
            for (int tb = 0; tb < 2; tb++) {
                uint32_t btile = sb + AT_T0 + (((kc < 4) ? 0 : 2) + tb) * 9216
                                 + (kc & 3) * 32 + b_lane;
                #pragma unroll
                for (int n2 = 0; n2 < 4; n2++) {
                    uint32_t b0, b1, b2, b3;
                    LDSM_X4(b0, b1, b2, b3, btile + n2 * (16 * 144));
                    uint32_t bv0[2] = {b0, b1}, bv1[2] = {b2, b3};
                    MMA_BF16(s[2 * n2],     av, bv0);
                    MMA_BF16(s[2 * n2 + 1], av, bv1);
                }
            }
        }
        // term 2: Ql x Bh
        #pragma unroll
        for (int kc = 0; kc < 8; kc++) {
            uint32_t av[4];
            uint32_t aaddr = sb + AT_QL + a_off + ((kc < 4) ? kc * 32 : (kc - 4) * 32 + 144);
            LDSM_X4(av[0], av[1], av[2], av[3], aaddr);
            uint32_t btile = sb + AT_T0 + ((kc < 4) ? 0 : 2) * 9216 + (kc & 3) * 32 + b_lane;
            #pragma unroll
            for (int n2 = 0; n2 < 4; n2++) {
                uint32_t b0, b1, b2, b3;
                LDSM_X4(b0, b1, b2, b3, btile + n2 * (16 * 144));
                uint32_t bv0[2] = {b0, b1}, bv1[2] = {b2, b3};
                MMA_BF16(s[2 * n2],     av, bv0);
                MMA_BF16(s[2 * n2 + 1], av, bv1);
            }
        }

        // ---- causal mask + online softmax (raw scores; scale folded into exp) ----
        float mxA = -1e30f, mxB = -1e30f;
        #pragma unroll
        for (int ni = 0; ni < 8; ni++) {
            int gc0 = k0 + ni * 8 + c2;
            if (gc0     > grA) s[ni][0] = -1e30f;
            if (gc0 + 1 > grA) s[ni][1] = -1e30f;
            if (gc0     > grB) s[ni][2] = -1e30f;
            if (gc0 + 1 > grB) s[ni][3] = -1e30f;
            mxA = fmaxf(mxA, fmaxf(s[ni][0], s[ni][1]));
            mxB = fmaxf(mxB, fmaxf(s[ni][2], s[ni][3]));
        }
        mxA = fmaxf(mxA, __shfl_xor_sync(0xffffffffu, mxA, 1));
        mxA = fmaxf(mxA, __shfl_xor_sync(0xffffffffu, mxA, 2));
        mxB = fmaxf(mxB, __shfl_xor_sync(0xffffffffu, mxB, 1));
        mxB = fmaxf(mxB, __shfl_xor_sync(0xffffffffu, mxB, 2));
        float mnA = fmaxf(mA, mxA), mnB = fmaxf(mB, mxB);
        float aA = exp2f((mA - mnA) * SCALE_EXP);
        float aB = exp2f((mB - mnB) * SCALE_EXP);
        mA = mnA; mB = mnB;
        lA *= aA; lB *= aB;
        #pragma unroll
        for (int ni = 0; ni < 8; ni++) {
            o[ni][0] *= aA; o[ni][1] *= aA; o[ni][2] *= aB; o[ni][3] *= aB;
        }

        // ---- exp + pack P (hi/lo) straight into A-fragment layout ----
        uint32_t ph[16], pl[16];
        float lsA = 0.f, lsB = 0.f;
        #pragma unroll
        for (int ni = 0; ni < 8; ni++) {
            float p0 = exp2f((s[ni][0] - mnA) * SCALE_EXP);
            float p1 = exp2f((s[ni][1] - mnA) * SCALE_EXP);
            float p2 = exp2f((s[ni][2] - mnB) * SCALE_EXP);
            float p3 = exp2f((s[ni][3] - mnB) * SCALE_EXP);
            lsA += p0 + p1; lsB += p2 + p3;
            float h0 = bfr(p0), h1 = bfr(p1), h2 = bfr(p2), h3 = bfr(p3);
            int base = (ni >> 1) * 4 + (ni & 1) * 2;
            ph[base]     = packbf(h0, h1);           // rows rA
            pl[base]     = packbf(p0 - h0, p1 - h1);
            ph[base + 1] = packbf(h2, h3);           // rows rB
            pl[base + 1] = packbf(p2 - h2, p3 - h3);
        }
        lA += lsA; lB += lsB;

        // ---- PV: o += Ph*Vh + Pl*Vh + Ph*Vl ----
        #pragma unroll
        for (int kpc = 0; kpc < 4; kpc++) {
            uint32_t* ap = &ph[kpc * 4];
            uint32_t* al = &pl[kpc * 4];
            const uint32_t vh_base = sb + AT_VH + kpc * (16 * 144) + v_lane;
            #pragma unroll
            for (int n2 = 0; n2 < 4; n2++) {
                uint32_t t0, t1, t2, t3;
                LDSM_X4T(t0, t1, t2, t3, vh_base + n2 * 32);
                uint32_t b0[2] = {t0, t1}, b1[2] = {t2, t3};
                MMA_BF16(o[2 * n2],     ap, b0);
                MMA_BF16(o[2 * n2 + 1], ap, b1);
                MMA_BF16(o[2 * n2],     al, b0);
                MMA_BF16(o[2 * n2 + 1], al, b1);
                LDSM_X4T(t0, t1, t2, t3, vh_base + 9216 + n2 * 32);
                uint32_t c0[2] = {t0, t1}, c1[2] = {t2, t3};
                MMA_BF16(o[2 * n2],     ap, c0);
                MMA_BF16(o[2 * n2 + 1], ap, c1);
            }
        }
    }

    // ---- epilogue: normalize, write ctx as bf16 hi/lo ----
    lA += __shfl_xor_sync(0xffffffffu, lA, 1);
    lA += __shfl_xor_sync(0xffffffffu, lA, 2);
    lB += __shfl_xor_sync(0xffffffffu, lB, 1);
    lB += __shfl_xor_sync(0xffffffffu, lB, 2);
    float invA = 1.f / lA, invB = 1.f / lB;

    if (grA < T_SEQ) {
        #pragma unroll
        for (int ni = 0; ni < 8; ni++) {
            size_t off = (size_t)grA * D_MODEL + h * HD + ni * 8 + c2;
            float v0 = o[ni][0] * invA, v1 = o[ni][1] * invA;
            float h0 = bfr(v0), h1 = bfr(v1);
            *(uint32_t*)(g_c_hi + off) = packbf(h0, h1);
            *(uint32_t*)(g_c_lo + off) = packbf(v0 - h0, v1 - h1);
        }
    }
    if (grB < T_SEQ) {
        #pragma unroll
        for (int ni = 0; ni < 8; ni++) {
            size_t off = (size_t)grB * D_MODEL + h * HD + ni * 8 + c2;
            float v0 = o[ni][2] * invB, v1 = o[ni][3] * invB;
            float h0 = bfr(v0), h1 = bfr(v1);
            *(uint32_t*)(g_c_hi + off) = packbf(h0, h1);
            *(uint32_t*)(g_c_lo + off) = packbf(v0 - h0, v1 - h1);
        }
    }
}

// ---------------------------------------------------------------------------
extern "C" void kernel_launch(void* const* d_in, const int* in_sizes, int n_in,
                              void* d_out, int out_size)
{
    const float* q  = (const float*)d_in[0];
    const float* k  = (const float*)d_in[1];
    const float* v  = (const float*)d_in[2];
    // d_in[3] = mask (int32 causal tril) — implied by the kernel, unused
    const float* Wq = (const float*)d_in[4];
    const float* bq = (const float*)d_in[5];
    const float* Wk = (const float*)d_in[6];
    const float* bk = (const float*)d_in[7];
    const float* Wv = (const float*)d_in[8];
    const float* bv = (const float*)d_in[9];
    const float* Er = (const float*)d_in[10];
    const float* Wo = (const float*)d_in[11];
    const float* bo = (const float*)d_in[12];
    float* out = (float*)d_out;

    cudaFuncSetAttribute(gemm_tc_kernel, cudaFuncAttributeMaxDynamicSharedMemorySize, GEMM_SMEM);
    cudaFuncSetAttribute(attn_tc_kernel, cudaFuncAttributeMaxDynamicSharedMemorySize, ATTN_SMEM);

    __nv_bfloat16 *xh, *xl, *wh, *wl, *eh, *el;
    cudaGetSymbolAddress((void**)&xh, g_x_hi);
    cudaGetSymbolAddress((void**)&xl, g_x_lo);
    cudaGetSymbolAddress((void**)&wh, g_w_hi);
    cudaGetSymbolAddress((void**)&wl, g_w_lo);
    cudaGetSymbolAddress((void**)&eh, g_er_hi);
    cudaGetSymbolAddress((void**)&el, g_er_lo);

    const int S = T_SEQ * D_MODEL;       // 2098176
    const int DD = D_MODEL * D_MODEL;    // 1048576
    const int E = T_SEQ * HD;            // 131136
    int gS = (S / 4 + 255) / 256, gD = (DD / 4 + 255) / 256, gE = (E / 4 + 255) / 256;

    cvt_kernel<<<gS, 256>>>(q, xh + 0 * (size_t)S, xl + 0 * (size_t)S, S);
    cvt_kernel<<<gS, 256>>>(k, xh + 1 * (size_t)S, xl + 1 * (size_t)S, S);
    cvt_kernel<<<gS, 256>>>(v, xh + 2 * (size_t)S, xl + 2 * (size_t)S, S);
    cvt_kernel<<<gD, 256>>>(Wq, wh + 0 * (size_t)DD, wl + 0 * (size_t)DD, DD);
    cvt_kernel<<<gD, 256>>>(Wk, wh + 1 * (size_t)DD, wl + 1 * (size_t)DD, DD);
    cvt_kernel<<<gD, 256>>>(Wv, wh + 2 * (size_t)DD, wl + 2 * (size_t)DD, DD);
    cvt_kernel<<<gD, 256>>>(Wo, wh + 3 * (size_t)DD, wl + 3 * (size_t)DD, DD);
    cvt_kernel<<<gE, 256>>>(Er, eh, el, E);

    dim3 gproj(17, 8, 3);
    gemm_tc_kernel<<<gproj, 256, GEMM_SMEM>>>(bq, bk, bv, nullptr, 0);

    attn_tc_kernel<<<17 * NH, 256, ATTN_SMEM>>>();

    dim3 gout(17, 8, 1);
    gemm_tc_kernel<<<gout, 256, GEMM_SMEM>>>(bo, nullptr, nullptr, out, 1);
}

// round 12
// speedup vs baseline: 2.8547x; 1.4024x over previous
#include <cuda_runtime.h>
#include <cuda_bf16.h>
#include <math.h>
#include <stdint.h>

#define T_SEQ 2049
#define D_MODEL 1024
#define NH 16
#define HD 64
#define SCALE_EXP 0.18033688011112042f   // 0.125 * log2(e)

// ---------------------------------------------------------------------------
// Scratch (__device__ globals; allocation-free rule)
// ---------------------------------------------------------------------------
__device__ __align__(128) __nv_bfloat16 g_x_hi[3 * T_SEQ * D_MODEL];
__device__ __align__(128) __nv_bfloat16 g_x_lo[3 * T_SEQ * D_MODEL];
__device__ __align__(128) __nv_bfloat16 g_w_hi[4 * D_MODEL * D_MODEL];
__device__ __align__(128) __nv_bfloat16 g_w_lo[4 * D_MODEL * D_MODEL];
__device__ __align__(128) __nv_bfloat16 g_c_hi[T_SEQ * D_MODEL];
__device__ __align__(128) __nv_bfloat16 g_c_lo[T_SEQ * D_MODEL];

__device__ __align__(128) __nv_bfloat16 g_qh_hi[NH * T_SEQ * HD];
__device__ __align__(128) __nv_bfloat16 g_qh_lo[NH * T_SEQ * HD];
__device__ __align__(128) __nv_bfloat16 g_kh_hi[NH * T_SEQ * HD];
__device__ __align__(128) __nv_bfloat16 g_kh_lo[NH * T_SEQ * HD];
__device__ __align__(128) __nv_bfloat16 g_vh_hi[NH * T_SEQ * HD];
__device__ __align__(128) __nv_bfloat16 g_vh_lo[NH * T_SEQ * HD];
__device__ __align__(128) __nv_bfloat16 g_er_hi[T_SEQ * HD];
__device__ __align__(128) __nv_bfloat16 g_er_lo[T_SEQ * HD];

// ---------------------------------------------------------------------------
// Helpers (all plain sm_80+ PTX: cp.async / ldmatrix / mma.sync)
// ---------------------------------------------------------------------------
__device__ __forceinline__ uint32_t s2u(const void* p) {
    return (uint32_t)__cvta_generic_to_shared(p);
}
__device__ __forceinline__ void cp16(uint32_t s, const void* g) {
    asm volatile("cp.async.cg.shared.global [%0], [%1], 16;" :: "r"(s), "l"(g));
}
__device__ __forceinline__ void cp16z(uint32_t s, const void* g, bool ok) {
    int sz = ok ? 16 : 0;
    asm volatile("cp.async.cg.shared.global [%0], [%1], 16, %2;" :: "r"(s), "l"(g), "r"(sz));
}
#define CP_COMMIT() asm volatile("cp.async.commit_group;" ::: "memory")
#define CP_WAIT(n)  asm volatile("cp.async.wait_group %0;" :: "n"(n) : "memory")

#define LDSM_X4(r0, r1, r2, r3, addr) \
    asm volatile("ldmatrix.sync.aligned.m8n8.x4.shared.b16 {%0,%1,%2,%3}, [%4];" \
        : "=r"(r0), "=r"(r1), "=r"(r2), "=r"(r3) : "r"(addr))
#define LDSM_X4T(r0, r1, r2, r3, addr) \
    asm volatile("ldmatrix.sync.aligned.m8n8.x4.trans.shared.b16 {%0,%1,%2,%3}, [%4];" \
        : "=r"(r0), "=r"(r1), "=r"(r2), "=r"(r3) : "r"(addr))
#define LDSM_X2(r0, r1, addr) \
    asm volatile("ldmatrix.sync.aligned.m8n8.x2.shared.b16 {%0,%1}, [%2];" \
        : "=r"(r0), "=r"(r1) : "r"(addr))

#define MMA_BF16(d, a, b) \
    asm volatile("mma.sync.aligned.m16n8k16.row.col.f32.bf16.bf16.f32 " \
        "{%0,%1,%2,%3}, {%4,%5,%6,%7}, {%8,%9}, {%0,%1,%2,%3};" \
        : "+f"((d)[0]), "+f"((d)[1]), "+f"((d)[2]), "+f"((d)[3]) \
        : "r"((a)[0]), "r"((a)[1]), "r"((a)[2]), "r"((a)[3]), \
          "r"((b)[0]), "r"((b)[1]))

__device__ __forceinline__ uint32_t packbf(float lo, float hi) {
    uint32_t d;
    asm("cvt.rn.bf16x2.f32 %0, %1, %2;" : "=r"(d) : "f"(hi), "f"(lo));
    return d;
}
__device__ __forceinline__ float bfr(float x) {
    return __bfloat162float(__float2bfloat16(x));
}

// ---------------------------------------------------------------------------
// Fused fp32 -> bf16 hi/lo conversion over 8 segments
// ---------------------------------------------------------------------------
struct CvtSegs {
    const float* src[8];
    __nv_bfloat16* hi[8];
    __nv_bfloat16* lo[8];
    int blk0[8];   // starting block of each segment
    int n[8];      // element count per segment
};

__global__ __launch_bounds__(256) void cvt_all_kernel(CvtSegs segs) {
    int b = blockIdx.x;
    int s = 0;
    #pragma unroll
    for (int i = 1; i < 8; i++) if (b >= segs.blk0[i]) s = i;
    int i = ((b - segs.blk0[s]) * 256 + threadIdx.x) * 4;
    if (i >= segs.n[s]) return;
    float4 v = *(const float4*)(segs.src[s] + i);
    float h0 = bfr(v.x), h1 = bfr(v.y), h2 = bfr(v.z), h3 = bfr(v.w);
    uint32_t* hp = (uint32_t*)(segs.hi[s] + i);
    uint32_t* lp = (uint32_t*)(segs.lo[s] + i);
    hp[0] = packbf(h0, h1); hp[1] = packbf(h2, h3);
    lp[0] = packbf(v.x - h0, v.y - h1); lp[1] = packbf(v.z - h2, v.w - h3);
}

// ---------------------------------------------------------------------------
// HMMA GEMM: D[m,n] = sum_k A[m,k]*B[n,k] + bias[n]
// bf16 split Ah*Bh + Ah*Bl + Al*Bh. Stage = {Ah,Al,Bh,Bl} for one k-chunk
// of 64; 16 chunks, 2-stage cp.async pipeline; 3 term-MMAs per fragment load.
// mode 0: proj (z = q/k/v) -> head-major bf16 hi/lo
// mode 1: out-proj -> fp32 row-major out_param
// ---------------------------------------------------------------------------
#define ROWB 144
#define TILEB (128 * ROWB)              // 18432
#define STAGEB (4 * TILEB)              // 73728
#define GEMM_SMEM (2 * STAGEB)          // 147456
#define NCHUNK 16

__global__ __launch_bounds__(256) void gemm_tc_kernel(
    const float* __restrict__ bias0, const float* __restrict__ bias1,
    const float* __restrict__ bias2, float* __restrict__ out_param, int mode)
{
    extern __shared__ __align__(128) char smem[];
    const uint32_t smem_base = s2u(smem);
    const int tid = threadIdx.x;
    const int wid = tid >> 5, lane = tid & 31;
    const int wm = (wid & 1) * 64;
    const int wn = (wid >> 1) * 32;
    const int m0 = blockIdx.x * 128, n0 = blockIdx.y * 128;

    const __nv_bfloat16 *Ah, *Al, *Bh, *Bl;
    const float* bias;
    float* outp = nullptr;
    __nv_bfloat16 *oh = nullptr, *ol = nullptr;
    const size_t S = (size_t)T_SEQ * D_MODEL, DD = (size_t)D_MODEL * D_MODEL;
    if (mode == 0) {
        int z = blockIdx.z;
        Ah = g_x_hi + z * S; Al = g_x_lo + z * S;
        Bh = g_w_hi + z * DD; Bl = g_w_lo + z * DD;
        bias = (z == 0) ? bias0 : (z == 1) ? bias1 : bias2;
        oh = (z == 0) ? g_qh_hi : (z == 1) ? g_kh_hi : g_vh_hi;
        ol = (z == 0) ? g_qh_lo : (z == 1) ? g_kh_lo : g_vh_lo;
    } else {
        Ah = g_c_hi; Al = g_c_lo;
        Bh = g_w_hi + 3 * DD; Bl = g_w_lo + 3 * DD;
        bias = bias0;
        outp = out_param;
    }

    const int lrow = tid >> 1;
    const int lc = (tid & 1) * 4;
    int tA = m0 + lrow; if (tA > T_SEQ - 1) tA = T_SEQ - 1;
    const size_t a_base = (size_t)tA * D_MODEL + lc * 8;
    const size_t b_base = (size_t)(n0 + lrow) * D_MODEL + lc * 8;
    const uint32_t s_off = (uint32_t)lrow * ROWB + lc * 16;

    float acc[4][4][4] = {};

    // stage loader: {Ah, Al, Bh, Bl} slices for k-chunk `ck`
    auto load_stage = [&](int stage, int ck) {
        const int k0 = ck * 64;
        const uint32_t s0 = smem_base + stage * STAGEB + s_off;
        const __nv_bfloat16* p0 = Ah + a_base + k0;
        const __nv_bfloat16* p1 = Al + a_base + k0;
        const __nv_bfloat16* p2 = Bh + b_base + k0;
        const __nv_bfloat16* p3 = Bl + b_base + k0;
        #pragma unroll
        for (int j = 0; j < 4; j++) {
            cp16(s0 + 0 * TILEB + j * 16, p0 + j * 8);
            cp16(s0 + 1 * TILEB + j * 16, p1 + j * 8);
            cp16(s0 + 2 * TILEB + j * 16, p2 + j * 8);
            cp16(s0 + 3 * TILEB + j * 16, p3 + j * 8);
        }
        CP_COMMIT();
    };

    load_stage(0, 0);

    for (int it = 0; it < NCHUNK; it++) {
        const int cur = it & 1;
        if (it + 1 < NCHUNK) {
            load_stage(cur ^ 1, it + 1);
            CP_WAIT(1);
        } else {
            CP_WAIT(0);
        }
        __syncthreads();

        const uint32_t st = smem_base + cur * STAGEB;
        const uint32_t aBaseH = st + (uint32_t)(wm + (lane & 15)) * ROWB + (lane >> 4) * 16;
        const uint32_t bBaseH = st + 2 * TILEB
                              + (uint32_t)(wn + (lane & 7)) * ROWB + ((lane >> 3) & 1) * 16;

        #pragma unroll
        for (int ks = 0; ks < 4; ks++) {
            uint32_t ah[4][4], al[4][4];
            #pragma unroll
            for (int mi = 0; mi < 4; mi++) {
                LDSM_X4(ah[mi][0], ah[mi][1], ah[mi][2], ah[mi][3],
                        aBaseH + mi * (16 * ROWB) + ks * 32);
                LDSM_X4(al[mi][0], al[mi][1], al[mi][2], al[mi][3],
                        aBaseH + TILEB + mi * (16 * ROWB) + ks * 32);
            }
            uint32_t bh[4][2], bl[4][2];
            #pragma unroll
            for (int ni = 0; ni < 4; ni++) {
                LDSM_X2(bh[ni][0], bh[ni][1], bBaseH + ni * (8 * ROWB) + ks * 32);
                LDSM_X2(bl[ni][0], bl[ni][1], bBaseH + TILEB + ni * (8 * ROWB) + ks * 32);
            }
            #pragma unroll
            for (int mi = 0; mi < 4; mi++)
                #pragma unroll
                for (int ni = 0; ni < 4; ni++) {
                    MMA_BF16(acc[mi][ni], ah[mi], bh[ni]);
                    MMA_BF16(acc[mi][ni], ah[mi], bl[ni]);
                    MMA_BF16(acc[mi][ni], al[mi], bh[ni]);
                }
        }
        __syncthreads();
    }

    const int r_in = lane >> 2, c_in = (lane & 3) * 2;
    #pragma unroll
    for (int mi = 0; mi < 4; mi++) {
        #pragma unroll
        for (int half = 0; half < 2; half++) {
            int t = m0 + wm + mi * 16 + r_in + half * 8;
            if (t >= T_SEQ) continue;
            #pragma unroll
            for (int ni = 0; ni < 4; ni++) {
                int n = n0 + wn + ni * 8 + c_in;
                float v0 = acc[mi][ni][half * 2 + 0] + bias[n];
                float v1 = acc[mi][ni][half * 2 + 1] + bias[n + 1];
                if (mode == 0) {
                    size_t off = (size_t)(n >> 6) * (T_SEQ * HD) + (size_t)t * HD + (n & 63);
                    float h0 = bfr(v0), h1 = bfr(v1);
                    *(uint32_t*)(oh + off) = packbf(h0, h1);
                    *(uint32_t*)(ol + off) = packbf(v0 - h0, v1 - h1);
                } else {
                    float* dst = outp + (size_t)t * D_MODEL + n;
                    dst[0] = v0; dst[1] = v1;
                }
            }
        }
    }
}

// ---------------------------------------------------------------------------
// Tensor-core flash attention with relative-position bias.
// Block: one head x 128 q-rows (8 warps x 16 rows). Key tiles of 64,
// double-buffered (2-stage cp.async ring). S = [Q|Qshift].[K|Er]^T, 3-term
// bf16 hi/lo split. Register softmax; PV = Ph*Vh + Pl*Vh + Ph*Vl.
// ---------------------------------------------------------------------------
#define AT_QH 0
#define AT_QL 18720                 // 130 * 144
#define AT_T0 37440
#define AT_STG 55296                // 6 tiles x 9216
#define ATTN_SMEM (AT_T0 + 2 * AT_STG)   // 148032

__global__ __launch_bounds__(256, 1) void attn_tc_kernel()
{
    extern __shared__ __align__(128) char smem[];
    const uint32_t sb = s2u(smem);
    const int tid = threadIdx.x;
    const int wid = tid >> 5, lane = tid & 31;
    const int bid = blockIdx.x;
    const int qi = 16 - (bid >> 4);          // heavy tiles first
    const int h = bid & 15;
    const int q0 = qi * 128;
    const size_t hoff = (size_t)h * (T_SEQ * HD);

    // ---- Q tile: 129 rows, hi + lo, zero-filled past T ----
    for (int idx = tid; idx < 2 * 1032; idx += 256) {
        int half = (idx >= 1032) ? 1 : 0;
        int s_ = idx - half * 1032;
        int row = s_ >> 3, ch = s_ & 7;
        int gr = q0 + row;
        bool ok = gr < T_SEQ; if (!ok) gr = T_SEQ - 1;
        const __nv_bfloat16* src = (half ? g_qh_lo : g_qh_hi) + hoff + (size_t)gr * HD + ch * 8;
        cp16z(sb + (half ? AT_QL : AT_QH) + row * 144 + ch * 16, src, ok);
    }
    CP_COMMIT();

    const int r = lane >> 2, c2 = (lane & 3) * 2;
    const int grA = q0 + wid * 16 + r, grB = grA + 8;
    const uint32_t a_off = (uint32_t)(wid * 16 + (lane & 15)) * 144 + (lane >> 4) * 16;
    const uint32_t b_lane = (uint32_t)((lane & 7) + ((lane >> 4) & 1) * 8) * 144 + ((lane >> 3) & 1) * 16;
    const uint32_t v_lane = (uint32_t)((lane & 7) + ((lane >> 3) & 1) * 8) * 144 + ((lane >> 4) & 1) * 16;

    float o[8][4] = {};
    float mA = -1e30f, mB = -1e30f, lA = 0.f, lB = 0.f;

    const int kmax = min(q0 + 127, T_SEQ - 1);
    const int nkt = kmax / 64 + 1;
    const int wlimit = q0 + wid * 16 + 15;

    const __nv_bfloat16* srcs[6] = { g_kh_hi + hoff, g_kh_lo + hoff, g_er_hi, g_er_lo,
                                     g_vh_hi + hoff, g_vh_lo + hoff };

    auto load_tiles = [&](int stage, int kt) {
        const int k0 = kt * 64;
        const uint32_t base = sb + AT_T0 + stage * AT_STG;
        for (int idx = tid; idx < 3072; idx += 256) {
            int tile = idx >> 9, sub = idx & 511, row = sub >> 3, ch = sub & 7;
            int gc = k0 + row; if (gc > T_SEQ - 1) gc = T_SEQ - 1;
            cp16(base + tile * 9216 + row * 144 + ch * 16,
                 srcs[tile] + (size_t)gc * HD + ch * 8);
        }
        CP_COMMIT();
    };

    load_tiles(0, 0);

    for (int kt = 0; kt < nkt; kt++) {
        const int cur = kt & 1;
        const int k0 = kt * 64;

        __syncthreads();                      // prior compute on stage cur^1 done
        if (kt + 1 < nkt) {
            load_tiles(cur ^ 1, kt + 1);
            CP_WAIT(1);
        } else {
            CP_WAIT(0);
        }
        __syncthreads();

        if (k0 > wlimit) continue;            // warp fully masked for this tile

        const uint32_t tb0 = sb + AT_T0 + cur * AT_STG;

        // ---- S accumulation: terms (Qh,Bh), (Qh,Bl), (Ql,Bh) ----
        float s[8][4] = {};
        #pragma unroll
        for (int kc = 0; kc < 8; kc++) {
            uint32_t av[4];
            uint32_t aaddr = sb + AT_QH + a_off + ((kc < 4) ? kc * 32 : (kc - 4) * 32 + 144);
            LDSM_X4(av[0], av[1], av[2], av[3], aaddr);
            #pragma unroll
            for (int tb = 0; tb < 2; tb++) {
                uint32_t btile = tb0 + (((kc < 4) ? 0 : 2) + tb) * 9216
                                 + (kc & 3) * 32 + b_lane;
                #pragma unroll
                for (int n2 = 0; n2 < 4; n2++) {
                    uint32_t b0, b1, b2, b3;
                    LDSM_X4(b0, b1, b2, b3, btile + n2 * (16 * 144));
                    uint32_t bv0[2] = {b0, b1}, bv1[2] = {b2, b3};
                    MMA_BF16(s[2 * n2],     av, bv0);
                    MMA_BF16(s[2 * n2 + 1], av, bv1);
                }
            }
        }
        #pragma unroll
        for (int kc = 0; kc < 8; kc++) {
            uint32_t av[4];
            uint32_t aaddr = sb + AT_QL + a_off + ((kc < 4) ? kc * 32 : (kc - 4) * 32 + 144);
            LDSM_X4(av[0], av[1], av[2], av[3], aaddr);
            uint32_t btile = tb0 + ((kc < 4) ? 0 : 2) * 9216 + (kc & 3) * 32 + b_lane;
            #pragma unroll
            for (int n2 = 0; n2 < 4; n2++) {
                uint32_t b0, b1, b2, b3;
                LDSM_X4(b0, b1, b2, b3, btile + n2 * (16 * 144));
                uint32_t bv0[2] = {b0, b1}, bv1[2] = {b2, b3};
                MMA_BF16(s[2 * n2],     av, bv0);
                MMA_BF16(s[2 * n2 + 1], av, bv1);
            }
        }

        // ---- causal mask + online softmax ----
        float mxA = -1e30f, mxB = -1e30f;
        #pragma unroll
        for (int ni = 0; ni < 8; ni++) {
            int gc0 = k0 + ni * 8 + c2;
            if (gc0     > grA) s[ni][0] = -1e30f;
            if (gc0 + 1 > grA) s[ni][1] = -1e30f;
            if (gc0     > grB) s[ni][2] = -1e30f;
            if (gc0 + 1 > grB) s[ni][3] = -1e30f;
            mxA = fmaxf(mxA, fmaxf(s[ni][0], s[ni][1]));
            mxB = fmaxf(mxB, fmaxf(s[ni][2], s[ni][3]));
        }
        mxA = fmaxf(mxA, __shfl_xor_sync(0xffffffffu, mxA, 1));
        mxA = fmaxf(mxA, __shfl_xor_sync(0xffffffffu, mxA, 2));
        mxB = fmaxf(mxB, __shfl_xor_sync(0xffffffffu, mxB, 1));
        mxB = fmaxf(mxB, __shfl_xor_sync(0xffffffffu, mxB, 2));
        float mnA = fmaxf(mA, mxA), mnB = fmaxf(mB, mxB);
        float aA = exp2f((mA - mnA) * SCALE_EXP);
        float aB = exp2f((mB - mnB) * SCALE_EXP);
        mA = mnA; mB = mnB;
        lA *= aA; lB *= aB;
        #pragma unroll
        for (int ni = 0; ni < 8; ni++) {
            o[ni][0] *= aA; o[ni][1] *= aA; o[ni][2] *= aB; o[ni][3] *= aB;
        }

        // ---- exp + pack P (hi/lo) into A-fragment layout ----
        uint32_t ph[16], pl[16];
        float lsA = 0.f, lsB = 0.f;
        #pragma unroll
        for (int ni = 0; ni < 8; ni++) {
            float p0 = exp2f((s[ni][0] - mnA) * SCALE_EXP);
            float p1 = exp2f((s[ni][1] - mnA) * SCALE_EXP);
            float p2 = exp2f((s[ni][2] - mnB) * SCALE_EXP);
            float p3 = exp2f((s[ni][3] - mnB) * SCALE_EXP);
            lsA += p0 + p1; lsB += p2 + p3;
            float h0 = bfr(p0), h1 = bfr(p1), h2 = bfr(p2), h3 = bfr(p3);
            int base = (ni >> 1) * 4 + (ni & 1) * 2;
            ph[base]     = packbf(h0, h1);
            pl[base]     = packbf(p0 - h0, p1 - h1);
            ph[base + 1] = packbf(h2, h3);
            pl[base + 1] = packbf(p2 - h2, p3 - h3);
        }
        lA += lsA; lB += lsB;

        // ---- PV: o += Ph*Vh + Pl*Vh + Ph*Vl ----
        #pragma unroll
        for (int kpc = 0; kpc < 4; kpc++) {
            uint32_t* ap = &ph[kpc * 4];
            uint32_t* al = &pl[kpc * 4];
            const uint32_t vh_base = tb0 + 4 * 9216 + kpc * (16 * 144) + v_lane;
            #pragma unroll
            for (int n2 = 0; n2 < 4; n2++) {
                uint32_t t0, t1, t2, t3;
                LDSM_X4T(t0, t1, t2, t3, vh_base + n2 * 32);
                uint32_t b0[2] = {t0, t1}, b1[2] = {t2, t3};
                MMA_BF16(o[2 * n2],     ap, b0);
                MMA_BF16(o[2 * n2 + 1], ap, b1);
                MMA_BF16(o[2 * n2],     al, b0);
                MMA_BF16(o[2 * n2 + 1], al, b1);
                LDSM_X4T(t0, t1, t2, t3, vh_base + 9216 + n2 * 32);
                uint32_t c0[2] = {t0, t1}, c1[2] = {t2, t3};
                MMA_BF16(o[2 * n2],     ap, c0);
                MMA_BF16(o[2 * n2 + 1], ap, c1);
            }
        }
    }

    // ---- epilogue: normalize, write ctx as bf16 hi/lo ----
    lA += __shfl_xor_sync(0xffffffffu, lA, 1);
    lA += __shfl_xor_sync(0xffffffffu, lA, 2);
    lB += __shfl_xor_sync(0xffffffffu, lB, 1);
    lB += __shfl_xor_sync(0xffffffffu, lB, 2);
    float invA = 1.f / lA, invB = 1.f / lB;

    if (grA < T_SEQ) {
        #pragma unroll
        for (int ni = 0; ni < 8; ni++) {
            size_t off = (size_t)grA * D_MODEL + h * HD + ni * 8 + c2;
            float v0 = o[ni][0] * invA, v1 = o[ni][1] * invA;
            float h0 = bfr(v0), h1 = bfr(v1);
            *(uint32_t*)(g_c_hi + off) = packbf(h0, h1);
            *(uint32_t*)(g_c_lo + off) = packbf(v0 - h0, v1 - h1);
        }
    }
    if (grB < T_SEQ) {
        #pragma unroll
        for (int ni = 0; ni < 8; ni++) {
            size_t off = (size_t)grB * D_MODEL + h * HD + ni * 8 + c2;
            float v0 = o[ni][2] * invB, v1 = o[ni][3] * invB;
            float h0 = bfr(v0), h1 = bfr(v1);
            *(uint32_t*)(g_c_hi + off) = packbf(h0, h1);
            *(uint32_t*)(g_c_lo + off) = packbf(v0 - h0, v1 - h1);
        }
    }
}

// ---------------------------------------------------------------------------
extern "C" void kernel_launch(void* const* d_in, const int* in_sizes, int n_in,
                              void* d_out, int out_size)
{
    const float* q  = (const float*)d_in[0];
    const float* k  = (const float*)d_in[1];
    const float* v  = (const float*)d_in[2];
    // d_in[3] = mask (int32 causal tril) — implied by the kernel, unused
    const float* Wq = (const float*)d_in[4];
    const float* bq = (const float*)d_in[5];
    const float* Wk = (const float*)d_in[6];
    const float* bk = (const float*)d_in[7];
    const float* Wv = (const float*)d_in[8];
    const float* bv = (const float*)d_in[9];
    const float* Er = (const float*)d_in[10];
    const float* Wo = (const float*)d_in[11];
    const float* bo = (const float*)d_in[12];
    float* out = (float*)d_out;

    cudaFuncSetAttribute(gemm_tc_kernel, cudaFuncAttributeMaxDynamicSharedMemorySize, GEMM_SMEM);
    cudaFuncSetAttribute(attn_tc_kernel, cudaFuncAttributeMaxDynamicSharedMemorySize, ATTN_SMEM);

    __nv_bfloat16 *xh, *xl, *wh, *wl, *eh, *el;
    cudaGetSymbolAddress((void**)&xh, g_x_hi);
    cudaGetSymbolAddress((void**)&xl, g_x_lo);
    cudaGetSymbolAddress((void**)&wh, g_w_hi);
    cudaGetSymbolAddress((void**)&wl, g_w_lo);
    cudaGetSymbolAddress((void**)&eh, g_er_hi);
    cudaGetSymbolAddress((void**)&el, g_er_lo);

    const int S = T_SEQ * D_MODEL;       // 2098176
    const int DD = D_MODEL * D_MODEL;    // 1048576
    const int E = T_SEQ * HD;            // 131136

    // fused hi/lo conversion: 8 segments, one launch
    CvtSegs cs;
    const float* srcs[8] = { q, k, v, Wq, Wk, Wv, Wo, Er };
    __nv_bfloat16* his[8] = { xh, xh + (size_t)S, xh + 2 * (size_t)S,
                              wh, wh + (size_t)DD, wh + 2 * (size_t)DD, wh + 3 * (size_t)DD, eh };
    __nv_bfloat16* los[8] = { xl, xl + (size_t)S, xl + 2 * (size_t)S,
                              wl, wl + (size_t)DD, wl + 2 * (size_t)DD, wl + 3 * (size_t)DD, el };
    int ns[8] = { S, S, S, DD, DD, DD, DD, E };
    int blk = 0;
    for (int i = 0; i < 8; i++) {
        cs.src[i] = srcs[i]; cs.hi[i] = his[i]; cs.lo[i] = los[i];
        cs.n[i] = ns[i]; cs.blk0[i] = blk;
        blk += (ns[i] / 4 + 255) / 256;
    }
    cvt_all_kernel<<<blk, 256>>>(cs);

    dim3 gproj(17, 8, 3);
    gemm_tc_kernel<<<gproj, 256, GEMM_SMEM>>>(bq, bk, bv, nullptr, 0);

    attn_tc_kernel<<<17 * NH, 256, ATTN_SMEM>>>();

    dim3 gout(17, 8, 1);
    gemm_tc_kernel<<<gout, 256, GEMM_SMEM>>>(bo, nullptr, nullptr, out, 1);
}

// round 14
// speedup vs baseline: 2.8632x; 1.0030x over previous
#include <cuda_runtime.h>
#include <cuda_bf16.h>
#include <math.h>
#include <stdint.h>

#define T_SEQ 2049
#define D_MODEL 1024
#define NH 16
#define HD 64
#define SCALE_EXP 0.18033688011112042f   // 0.125 * log2(e)

// ---------------------------------------------------------------------------
// Scratch (__device__ globals; allocation-free rule)
// ---------------------------------------------------------------------------
__device__ __align__(128) __nv_bfloat16 g_x_hi[3 * T_SEQ * D_MODEL];
__device__ __align__(128) __nv_bfloat16 g_x_lo[3 * T_SEQ * D_MODEL];
__device__ __align__(128) __nv_bfloat16 g_w_hi[4 * D_MODEL * D_MODEL];
__device__ __align__(128) __nv_bfloat16 g_w_lo[4 * D_MODEL * D_MODEL];
__device__ __align__(128) __nv_bfloat16 g_c_hi[T_SEQ * D_MODEL];
__device__ __align__(128) __nv_bfloat16 g_c_lo[T_SEQ * D_MODEL];

__device__ __align__(128) __nv_bfloat16 g_qh_hi[NH * T_SEQ * HD];
__device__ __align__(128) __nv_bfloat16 g_qh_lo[NH * T_SEQ * HD];
__device__ __align__(128) __nv_bfloat16 g_kh_hi[NH * T_SEQ * HD];
__device__ __align__(128) __nv_bfloat16 g_kh_lo[NH * T_SEQ * HD];
__device__ __align__(128) __nv_bfloat16 g_vh_hi[NH * T_SEQ * HD];
__device__ __align__(128) __nv_bfloat16 g_vh_lo[NH * T_SEQ * HD];
__device__ __align__(128) __nv_bfloat16 g_er_hi[T_SEQ * HD];
__device__ __align__(128) __nv_bfloat16 g_er_lo[T_SEQ * HD];

// ---------------------------------------------------------------------------
// Helpers (all plain sm_80+ PTX: cp.async / ldmatrix / mma.sync)
// ---------------------------------------------------------------------------
__device__ __forceinline__ uint32_t s2u(const void* p) {
    return (uint32_t)__cvta_generic_to_shared(p);
}
__device__ __forceinline__ void cp16(uint32_t s, const void* g) {
    asm volatile("cp.async.cg.shared.global [%0], [%1], 16;" :: "r"(s), "l"(g));
}
__device__ __forceinline__ void cp16z(uint32_t s, const void* g, bool ok) {
    int sz = ok ? 16 : 0;
    asm volatile("cp.async.cg.shared.global [%0], [%1], 16, %2;" :: "r"(s), "l"(g), "r"(sz));
}
#define CP_COMMIT() asm volatile("cp.async.commit_group;" ::: "memory")
#define CP_WAIT(n)  asm volatile("cp.async.wait_group %0;" :: "n"(n) : "memory")

#define LDSM_X4(r0, r1, r2, r3, addr) \
    asm volatile("ldmatrix.sync.aligned.m8n8.x4.shared.b16 {%0,%1,%2,%3}, [%4];" \
        : "=r"(r0), "=r"(r1), "=r"(r2), "=r"(r3) : "r"(addr))
#define LDSM_X4T(r0, r1, r2, r3, addr) \
    asm volatile("ldmatrix.sync.aligned.m8n8.x4.trans.shared.b16 {%0,%1,%2,%3}, [%4];" \
        : "=r"(r0), "=r"(r1), "=r"(r2), "=r"(r3) : "r"(addr))
#define LDSM_X2(r0, r1, addr) \
    asm volatile("ldmatrix.sync.aligned.m8n8.x2.shared.b16 {%0,%1}, [%2];" \
        : "=r"(r0), "=r"(r1) : "r"(addr))

#define MMA_BF16(d, a, b) \
    asm volatile("mma.sync.aligned.m16n8k16.row.col.f32.bf16.bf16.f32 " \
        "{%0,%1,%2,%3}, {%4,%5,%6,%7}, {%8,%9}, {%0,%1,%2,%3};" \
        : "+f"((d)[0]), "+f"((d)[1]), "+f"((d)[2]), "+f"((d)[3]) \
        : "r"((a)[0]), "r"((a)[1]), "r"((a)[2]), "r"((a)[3]), \
          "r"((b)[0]), "r"((b)[1]))

__device__ __forceinline__ uint32_t packbf(float lo, float hi) {
    uint32_t d;
    asm("cvt.rn.bf16x2.f32 %0, %1, %2;" : "=r"(d) : "f"(hi), "f"(lo));
    return d;
}
__device__ __forceinline__ float bfr(float x) {
    return __bfloat162float(__float2bfloat16(x));
}

// ---------------------------------------------------------------------------
// Fused fp32 -> bf16 hi/lo conversion over 8 segments
// ---------------------------------------------------------------------------
struct CvtSegs {
    const float* src[8];
    __nv_bfloat16* hi[8];
    __nv_bfloat16* lo[8];
    int blk0[8];
    int n[8];
};

__global__ __launch_bounds__(256) void cvt_all_kernel(CvtSegs segs) {
    int b = blockIdx.x;
    int s = 0;
    #pragma unroll
    for (int i = 1; i < 8; i++) if (b >= segs.blk0[i]) s = i;
    int i = ((b - segs.blk0[s]) * 256 + threadIdx.x) * 4;
    if (i >= segs.n[s]) return;
    float4 v = *(const float4*)(segs.src[s] + i);
    float h0 = bfr(v.x), h1 = bfr(v.y), h2 = bfr(v.z), h3 = bfr(v.w);
    uint32_t* hp = (uint32_t*)(segs.hi[s] + i);
    uint32_t* lp = (uint32_t*)(segs.lo[s] + i);
    hp[0] = packbf(h0, h1); hp[1] = packbf(h2, h3);
    lp[0] = packbf(v.x - h0, v.y - h1); lp[1] = packbf(v.z - h2, v.w - h3);
}

// ---------------------------------------------------------------------------
// HMMA GEMM: D[m,n] = sum_k A[m,k]*B[n,k] + bias[n]
// bf16 split Ah*Bh + Ah*Bl + Al*Bh; per k-slice MMAs issued TERM-MAJOR so
// same-accumulator reuse distance is 16 independent MMAs (RAW chains broken).
// ---------------------------------------------------------------------------
#define ROWB 144
#define TILEB (128 * ROWB)              // 18432
#define STAGEB (4 * TILEB)              // 73728
#define GEMM_SMEM (2 * STAGEB)          // 147456
#define NCHUNK 16

__global__ __launch_bounds__(256) void gemm_tc_kernel(
    const float* __restrict__ bias0, const float* __restrict__ bias1,
    const float* __restrict__ bias2, float* __restrict__ out_param, int mode)
{
    extern __shared__ __align__(128) char smem[];
    const uint32_t smem_base = s2u(smem);
    const int tid = threadIdx.x;
    const int wid = tid >> 5, lane = tid & 31;
    const int wm = (wid & 1) * 64;
    const int wn = (wid >> 1) * 32;
    const int m0 = blockIdx.x * 128, n0 = blockIdx.y * 128;

    const __nv_bfloat16 *Ah, *Al, *Bh, *Bl;
    const float* bias;
    float* outp = nullptr;
    __nv_bfloat16 *oh = nullptr, *ol = nullptr;
    const size_t S = (size_t)T_SEQ * D_MODEL, DD = (size_t)D_MODEL * D_MODEL;
    if (mode == 0) {
        int z = blockIdx.z;
        Ah = g_x_hi + z * S; Al = g_x_lo + z * S;
        Bh = g_w_hi + z * DD; Bl = g_w_lo + z * DD;
        bias = (z == 0) ? bias0 : (z == 1) ? bias1 : bias2;
        oh = (z == 0) ? g_qh_hi : (z == 1) ? g_kh_hi : g_vh_hi;
        ol = (z == 0) ? g_qh_lo : (z == 1) ? g_kh_lo : g_vh_lo;
    } else {
        Ah = g_c_hi; Al = g_c_lo;
        Bh = g_w_hi + 3 * DD; Bl = g_w_lo + 3 * DD;
        bias = bias0;
        outp = out_param;
    }

    const int lrow = tid >> 1;
    const int lc = (tid & 1) * 4;
    int tA = m0 + lrow; if (tA > T_SEQ - 1) tA = T_SEQ - 1;
    const size_t a_base = (size_t)tA * D_MODEL + lc * 8;
    const size_t b_base = (size_t)(n0 + lrow) * D_MODEL + lc * 8;
    const uint32_t s_off = (uint32_t)lrow * ROWB + lc * 16;

    float acc[4][4][4] = {};

    auto load_stage = [&](int stage, int ck) {
        const int k0 = ck * 64;
        const uint32_t s0 = smem_base + stage * STAGEB + s_off;
        const __nv_bfloat16* p0 = Ah + a_base + k0;
        const __nv_bfloat16* p1 = Al + a_base + k0;
        const __nv_bfloat16* p2 = Bh + b_base + k0;
        const __nv_bfloat16* p3 = Bl + b_base + k0;
        #pragma unroll
        for (int j = 0; j < 4; j++) {
            cp16(s0 + 0 * TILEB + j * 16, p0 + j * 8);
            cp16(s0 + 1 * TILEB + j * 16, p1 + j * 8);
            cp16(s0 + 2 * TILEB + j * 16, p2 + j * 8);
            cp16(s0 + 3 * TILEB + j * 16, p3 + j * 8);
        }
        CP_COMMIT();
    };

    load_stage(0, 0);

    for (int it = 0; it < NCHUNK; it++) {
        const int cur = it & 1;
        if (it + 1 < NCHUNK) {
            load_stage(cur ^ 1, it + 1);
            CP_WAIT(1);
        } else {
            CP_WAIT(0);
        }
        __syncthreads();

        const uint32_t st = smem_base + cur * STAGEB;
        const uint32_t aBaseH = st + (uint32_t)(wm + (lane & 15)) * ROWB + (lane >> 4) * 16;
        const uint32_t bBaseH = st + 2 * TILEB
                              + (uint32_t)(wn + (lane & 7)) * ROWB + ((lane >> 3) & 1) * 16;

        #pragma unroll
        for (int ks = 0; ks < 4; ks++) {
            uint32_t ah[4][4], al[4][4];
            #pragma unroll
            for (int mi = 0; mi < 4; mi++) {
                LDSM_X4(ah[mi][0], ah[mi][1], ah[mi][2], ah[mi][3],
                        aBaseH + mi * (16 * ROWB) + ks * 32);
                LDSM_X4(al[mi][0], al[mi][1], al[mi][2], al[mi][3],
                        aBaseH + TILEB + mi * (16 * ROWB) + ks * 32);
            }
            uint32_t bh[4][2], bl[4][2];
            #pragma unroll
            for (int ni = 0; ni < 4; ni++) {
                LDSM_X2(bh[ni][0], bh[ni][1], bBaseH + ni * (8 * ROWB) + ks * 32);
                LDSM_X2(bl[ni][0], bl[ni][1], bBaseH + TILEB + ni * (8 * ROWB) + ks * 32);
            }
            // term-major: 16 independent MMAs between same-acc reuse
            #pragma unroll
            for (int mi = 0; mi < 4; mi++)
                #pragma unroll
                for (int ni = 0; ni < 4; ni++)
                    MMA_BF16(acc[mi][ni], ah[mi], bh[ni]);
            #pragma unroll
            for (int mi = 0; mi < 4; mi++)
                #pragma unroll
                for (int ni = 0; ni < 4; ni++)
                    MMA_BF16(acc[mi][ni], ah[mi], bl[ni]);
            #pragma unroll
            for (int mi = 0; mi < 4; mi++)
                #pragma unroll
                for (int ni = 0; ni < 4; ni++)
                    MMA_BF16(acc[mi][ni], al[mi], bh[ni]);
        }
        __syncthreads();
    }

    const int r_in = lane >> 2, c_in = (lane & 3) * 2;
    #pragma unroll
    for (int mi = 0; mi < 4; mi++) {
        #pragma unroll
        for (int half = 0; half < 2; half++) {
            int t = m0 + wm + mi * 16 + r_in + half * 8;
            if (t >= T_SEQ) continue;
            #pragma unroll
            for (int ni = 0; ni < 4; ni++) {
                int n = n0 + wn + ni * 8 + c_in;
                float v0 = acc[mi][ni][half * 2 + 0] + bias[n];
                float v1 = acc[mi][ni][half * 2 + 1] + bias[n + 1];
                if (mode == 0) {
                    size_t off = (size_t)(n >> 6) * (T_SEQ * HD) + (size_t)t * HD + (n & 63);
                    float h0 = bfr(v0), h1 = bfr(v1);
                    *(uint32_t*)(oh + off) = packbf(h0, h1);
                    *(uint32_t*)(ol + off) = packbf(v0 - h0, v1 - h1);
                } else {
                    float* dst = outp + (size_t)t * D_MODEL + n;
                    dst[0] = v0; dst[1] = v1;
                }
            }
        }
    }
}

// ---------------------------------------------------------------------------
// Tensor-core flash attention with relative-position bias.
// PV MMAs reordered term-major (V fragments preloaded per k-slice).
// ---------------------------------------------------------------------------
#define AT_QH 0
#define AT_QL 18720                 // 130 * 144
#define AT_T0 37440
#define AT_STG 55296                // 6 tiles x 9216
#define ATTN_SMEM (AT_T0 + 2 * AT_STG)   // 148032

__global__ __launch_bounds__(256, 1) void attn_tc_kernel()
{
    extern __shared__ __align__(128) char smem[];
    const uint32_t sb = s2u(smem);
    const int tid = threadIdx.x;
    const int wid = tid >> 5, lane = tid & 31;
    const int bid = blockIdx.x;
    const int qi = 16 - (bid >> 4);          // heavy tiles first
    const int h = bid & 15;
    const int q0 = qi * 128;
    const size_t hoff = (size_t)h * (T_SEQ * HD);

    // ---- Q tile: 129 rows, hi + lo, zero-filled past T ----
    for (int idx = tid; idx < 2 * 1032; idx += 256) {
        int half = (idx >= 1032) ? 1 : 0;
        int s_ = idx - half * 1032;
        int row = s_ >> 3, ch = s_ & 7;
        int gr = q0 + row;
        bool ok = gr < T_SEQ; if (!ok) gr = T_SEQ - 1;
        const __nv_bfloat16* src = (half ? g_qh_lo : g_qh_hi) + hoff + (size_t)gr * HD + ch * 8;
        cp16z(sb + (half ? AT_QL : AT_QH) + row * 144 + ch * 16, src, ok);
    }
    CP_COMMIT();

    const int r = lane >> 2, c2 = (lane & 3) * 2;
    const int grA = q0 + wid * 16 + r, grB = grA + 8;
    const uint32_t a_off = (uint32_t)(wid * 16 + (lane & 15)) * 144 + (lane >> 4) * 16;
    const uint32_t b_lane = (uint32_t)((lane & 7) + ((lane >> 4) & 1) * 8) * 144 + ((lane >> 3) & 1) * 16;
    const uint32_t v_lane = (uint32_t)((lane & 7) + ((lane >> 3) & 1) * 8) * 144 + ((lane >> 4) & 1) * 16;

    float o[8][4] = {};
    float mA = -1e30f, mB = -1e30f, lA = 0.f, lB = 0.f;

    const int kmax = min(q0 + 127, T_SEQ - 1);
    const int nkt = kmax / 64 + 1;
    const int wlimit = q0 + wid * 16 + 15;

    const __nv_bfloat16* srcs[6] = { g_kh_hi + hoff, g_kh_lo + hoff, g_er_hi, g_er_lo,
                                     g_vh_hi + hoff, g_vh_lo + hoff };

    auto load_tiles = [&](int stage, int kt) {
        const int k0 = kt * 64;
        const uint32_t base = sb + AT_T0 + stage * AT_STG;
        for (int idx = tid; idx < 3072; idx += 256) {
            int tile = idx >> 9, sub = idx & 511, row = sub >> 3, ch = sub & 7;
            int gc = k0 + row; if (gc > T_SEQ - 1) gc = T_SEQ - 1;
            cp16(base + tile * 9216 + row * 144 + ch * 16,
                 srcs[tile] + (size_t)gc * HD + ch * 8);
        }
        CP_COMMIT();
    };

    load_tiles(0, 0);

    for (int kt = 0; kt < nkt; kt++) {
        const int cur = kt & 1;
        const int k0 = kt * 64;

        __syncthreads();
        if (kt + 1 < nkt) {
            load_tiles(cur ^ 1, kt + 1);
            CP_WAIT(1);
        } else {
            CP_WAIT(0);
        }
        __syncthreads();

        if (k0 > wlimit) continue;

        const uint32_t tb0 = sb + AT_T0 + cur * AT_STG;

        // ---- S accumulation: terms (Qh,Bh), (Qh,Bl), (Ql,Bh) ----
        float s[8][4] = {};
        #pragma unroll
        for (int kc = 0; kc < 8; kc++) {
            uint32_t av[4];
            uint32_t aaddr = sb + AT_QH + a_off + ((kc < 4) ? kc * 32 : (kc - 4) * 32 + 144);
            LDSM_X4(av[0], av[1], av[2], av[3], aaddr);
            #pragma unroll
            for (int tb = 0; tb < 2; tb++) {
                uint32_t btile = tb0 + (((kc < 4) ? 0 : 2) + tb) * 9216
                                 + (kc & 3) * 32 + b_lane;
                #pragma unroll
                for (int n2 = 0; n2 < 4; n2++) {
                    uint32_t b0, b1, b2, b3;
                    LDSM_X4(b0, b1, b2, b3, btile + n2 * (16 * 144));
                    uint32_t bv0[2] = {b0, b1}, bv1[2] = {b2, b3};
                    MMA_BF16(s[2 * n2],     av, bv0);
                    MMA_BF16(s[2 * n2 + 1], av, bv1);
                }
            }
        }
        #pragma unroll
        for (int kc = 0; kc < 8; kc++) {
            uint32_t av[4];
            uint32_t aaddr = sb + AT_QL + a_off + ((kc < 4) ? kc * 32 : (kc - 4) * 32 + 144);
            LDSM_X4(av[0], av[1], av[2], av[3], aaddr);
            uint32_t btile = tb0 + ((kc < 4) ? 0 : 2) * 9216 + (kc & 3) * 32 + b_lane;
            #pragma unroll
            for (int n2 = 0; n2 < 4; n2++) {
                uint32_t b0, b1, b2, b3;
                LDSM_X4(b0, b1, b2, b3, btile + n2 * (16 * 144));
                uint32_t bv0[2] = {b0, b1}, bv1[2] = {b2, b3};
                MMA_BF16(s[2 * n2],     av, bv0);
                MMA_BF16(s[2 * n2 + 1], av, bv1);
            }
        }

        // ---- causal mask + online softmax ----
        float mxA = -1e30f, mxB = -1e30f;
        #pragma unroll
        for (int ni = 0; ni < 8; ni++) {
            int gc0 = k0 + ni * 8 + c2;
            if (gc0     > grA) s[ni][0] = -1e30f;
            if (gc0 + 1 > grA) s[ni][1] = -1e30f;
            if (gc0     > grB) s[ni][2] = -1e30f;
            if (gc0 + 1 > grB) s[ni][3] = -1e30f;
            mxA = fmaxf(mxA, fmaxf(s[ni][0], s[ni][1]));
            mxB = fmaxf(mxB, fmaxf(s[ni][2], s[ni][3]));
        }
        mxA = fmaxf(mxA, __shfl_xor_sync(0xffffffffu, mxA, 1));
        mxA = fmaxf(mxA, __shfl_xor_sync(0xffffffffu, mxA, 2));
        mxB = fmaxf(mxB, __shfl_xor_sync(0xffffffffu, mxB, 1));
        mxB = fmaxf(mxB, __shfl_xor_sync(0xffffffffu, mxB, 2));
        float mnA = fmaxf(mA, mxA), mnB = fmaxf(mB, mxB);
        float aA = exp2f((mA - mnA) * SCALE_EXP);
        float aB = exp2f((mB - mnB) * SCALE_EXP);
        mA = mnA; mB = mnB;
        lA *= aA; lB *= aB;
        #pragma unroll
        for (int ni = 0; ni < 8; ni++) {
            o[ni][0] *= aA; o[ni][1] *= aA; o[ni][2] *= aB; o[ni][3] *= aB;
        }

        // ---- exp + pack P (hi/lo) into A-fragment layout ----
        uint32_t ph[16], pl[16];
        float lsA = 0.f, lsB = 0.f;
        #pragma unroll
        for (int ni = 0; ni < 8; ni++) {
            float p0 = exp2f((s[ni][0] - mnA) * SCALE_EXP);
            float p1 = exp2f((s[ni][1] - mnA) * SCALE_EXP);
            float p2 = exp2f((s[ni][2] - mnB) * SCALE_EXP);
            float p3 = exp2f((s[ni][3] - mnB) * SCALE_EXP);
            lsA += p0 + p1; lsB += p2 + p3;
            float h0 = bfr(p0), h1 = bfr(p1), h2 = bfr(p2), h3 = bfr(p3);
            int base = (ni >> 1) * 4 + (ni & 1) * 2;
            ph[base]     = packbf(h0, h1);
            pl[base]     = packbf(p0 - h0, p1 - h1);
            ph[base + 1] = packbf(h2, h3);
            pl[base + 1] = packbf(p2 - h2, p3 - h3);
        }
        lA += lsA; lB += lsB;

        // ---- PV: preload V frags, then term-major Ph*Vh, Pl*Vh, Ph*Vl ----
        #pragma unroll
        for (int kpc = 0; kpc < 4; kpc++) {
            uint32_t* ap = &ph[kpc * 4];
            uint32_t* al = &pl[kpc * 4];
            const uint32_t vh_base = tb0 + 4 * 9216 + kpc * (16 * 144) + v_lane;
            uint32_t vh[4][4], vl[4][4];
            #pragma unroll
            for (int n2 = 0; n2 < 4; n2++) {
                LDSM_X4T(vh[n2][0], vh[n2][1], vh[n2][2], vh[n2][3], vh_base + n2 * 32);
                LDSM_X4T(vl[n2][0], vl[n2][1], vl[n2][2], vl[n2][3], vh_base + 9216 + n2 * 32);
            }
            #pragma unroll
            for (int n2 = 0; n2 < 4; n2++) {
                MMA_BF16(o[2 * n2],     ap, &vh[n2][0]);
                MMA_BF16(o[2 * n2 + 1], ap, &vh[n2][2]);
            }
            #pragma unroll
            for (int n2 = 0; n2 < 4; n2++) {
                MMA_BF16(o[2 * n2],     al, &vh[n2][0]);
                MMA_BF16(o[2 * n2 + 1], al, &vh[n2][2]);
            }
            #pragma unroll
            for (int n2 = 0; n2 < 4; n2++) {
                MMA_BF16(o[2 * n2],     ap, &vl[n2][0]);
                MMA_BF16(o[2 * n2 + 1], ap, &vl[n2][2]);
            }
        }
    }

    // ---- epilogue: normalize, write ctx as bf16 hi/lo ----
    lA += __shfl_xor_sync(0xffffffffu, lA, 1);
    lA += __shfl_xor_sync(0xffffffffu, lA, 2);
    lB += __shfl_xor_sync(0xffffffffu, lB, 1);
    lB += __shfl_xor_sync(0xffffffffu, lB, 2);
    float invA = 1.f / lA, invB = 1.f / lB;

    if (grA < T_SEQ) {
        #pragma unroll
        for (int ni = 0; ni < 8; ni++) {
            size_t off = (size_t)grA * D_MODEL + h * HD + ni * 8 + c2;
            float v0 = o[ni][0] * invA, v1 = o[ni][1] * invA;
            float h0 = bfr(v0), h1 = bfr(v1);
            *(uint32_t*)(g_c_hi + off) = packbf(h0, h1);
            *(uint32_t*)(g_c_lo + off) = packbf(v0 - h0, v1 - h1);
        }
    }
    if (grB < T_SEQ) {
        #pragma unroll
        for (int ni = 0; ni < 8; ni++) {
            size_t off = (size_t)grB * D_MODEL + h * HD + ni * 8 + c2;
            float v0 = o[ni][2] * invB, v1 = o[ni][3] * invB;
            float h0 = bfr(v0), h1 = bfr(v1);
            *(uint32_t*)(g_c_hi + off) = packbf(h0, h1);
            *(uint32_t*)(g_c_lo + off) = packbf(v0 - h0, v1 - h1);
        }
    }
}

// ---------------------------------------------------------------------------
extern "C" void kernel_launch(void* const* d_in, const int* in_sizes, int n_in,
                              void* d_out, int out_size)
{
    const float* q  = (const float*)d_in[0];
    const float* k  = (const float*)d_in[1];
    const float* v  = (const float*)d_in[2];
    // d_in[3] = mask (int32 causal tril) — implied by the kernel, unused
    const float* Wq = (const float*)d_in[4];
    const float* bq = (const float*)d_in[5];
    const float* Wk = (const float*)d_in[6];
    const float* bk = (const float*)d_in[7];
    const float* Wv = (const float*)d_in[8];
    const float* bv = (const float*)d_in[9];
    const float* Er = (const float*)d_in[10];
    const float* Wo = (const float*)d_in[11];
    const float* bo = (const float*)d_in[12];
    float* out = (float*)d_out;

    cudaFuncSetAttribute(gemm_tc_kernel, cudaFuncAttributeMaxDynamicSharedMemorySize, GEMM_SMEM);
    cudaFuncSetAttribute(attn_tc_kernel, cudaFuncAttributeMaxDynamicSharedMemorySize, ATTN_SMEM);

    __nv_bfloat16 *xh, *xl, *wh, *wl, *eh, *el;
    cudaGetSymbolAddress((void**)&xh, g_x_hi);
    cudaGetSymbolAddress((void**)&xl, g_x_lo);
    cudaGetSymbolAddress((void**)&wh, g_w_hi);
    cudaGetSymbolAddress((void**)&wl, g_w_lo);
    cudaGetSymbolAddress((void**)&eh, g_er_hi);
    cudaGetSymbolAddress((void**)&el, g_er_lo);

    const int S = T_SEQ * D_MODEL;       // 2098176
    const int DD = D_MODEL * D_MODEL;    // 1048576
    const int E = T_SEQ * HD;            // 131136

    CvtSegs cs;
    const float* srcs[8] = { q, k, v, Wq, Wk, Wv, Wo, Er };
    __nv_bfloat16* his[8] = { xh, xh + (size_t)S, xh + 2 * (size_t)S,
                              wh, wh + (size_t)DD, wh + 2 * (size_t)DD, wh + 3 * (size_t)DD, eh };
    __nv_bfloat16* los[8] = { xl, xl + (size_t)S, xl + 2 * (size_t)S,
                              wl, wl + (size_t)DD, wl + 2 * (size_t)DD, wl + 3 * (size_t)DD, el };
    int ns[8] = { S, S, S, DD, DD, DD, DD, E };
    int blk = 0;
    for (int i = 0; i < 8; i++) {
        cs.src[i] = srcs[i]; cs.hi[i] = his[i]; cs.lo[i] = los[i];
        cs.n[i] = ns[i]; cs.blk0[i] = blk;
        blk += (ns[i] / 4 + 255) / 256;
    }
    cvt_all_kernel<<<blk, 256>>>(cs);

    dim3 gproj(17, 8, 3);
    gemm_tc_kernel<<<gproj, 256, GEMM_SMEM>>>(bq, bk, bv, nullptr, 0);

    attn_tc_kernel<<<17 * NH, 256, ATTN_SMEM>>>();

    dim3 gout(17, 8, 1);
    gemm_tc_kernel<<<gout, 256, GEMM_SMEM>>>(bo, nullptr, nullptr, out, 1);
}